// round 5
// baseline (speedup 1.0000x reference)
#include <cuda_runtime.h>
#include <math.h>

#define NN 20000
#define EE 160000
#define CC 1024

// ---------------- scratch (__device__ globals; no allocations allowed) ------
__device__ __align__(16) float g_deg[NN];
__device__ __align__(16) float g_dis[NN];
__device__ int   g_cnt[NN];
__device__ int   g_rp[NN + 1];
__device__ int   g_cur[NN];
__device__ int   g_col[EE];
__device__ __align__(16) float g_val[EE];

__device__ __align__(16) float g_T1x[(size_t)NN * CC];
__device__ __align__(16) float g_T2x[(size_t)NN * CC];
__device__ __align__(16) float g_T1h[(size_t)NN * CC];
__device__ __align__(16) float g_T2h[(size_t)NN * CC];   // later reused as H*R
__device__ __align__(16) float g_Zp[(size_t)NN * CC];
__device__ __align__(16) float g_Rp[(size_t)NN * CC];
__device__ __align__(16) float g_Hp[(size_t)NN * CC];

// ---------------- graph normalization + CSR build ---------------------------
__global__ void k_zero() {
    int i = blockIdx.x * 256 + threadIdx.x;
    if (i < NN) { g_deg[i] = 0.0f; g_cnt[i] = 0; }
}

__global__ void k_deg(const int* __restrict__ src, const int* __restrict__ dst,
                      const float* __restrict__ ew) {
    int e = blockIdx.x * 256 + threadIdx.x;
    if (e < EE) {
        int s = src[e], d = dst[e];
        float w = (s == d) ? 0.0f : ew[e];
        atomicAdd(&g_deg[s], w);
        atomicAdd(&g_cnt[d], 1);
    }
}

__global__ void k_dis() {
    int i = blockIdx.x * 256 + threadIdx.x;
    if (i < NN) {
        float d = g_deg[i];
        g_dis[i] = (d > 0.0f) ? rsqrtf(d) : 0.0f;
    }
}

// exclusive scan of g_cnt -> g_rp / g_cur, single block of 1024 threads
__global__ void k_scan() {
    __shared__ int s[1024];
    __shared__ int sh_carry;
    int tid = threadIdx.x;
    if (tid == 0) sh_carry = 0;
    __syncthreads();
    for (int base = 0; base < NN; base += 1024) {
        int i = base + tid;
        int v = (i < NN) ? g_cnt[i] : 0;
        s[tid] = v;
        __syncthreads();
        for (int off = 1; off < 1024; off <<= 1) {
            int t = (tid >= off) ? s[tid - off] : 0;
            __syncthreads();
            s[tid] += t;
            __syncthreads();
        }
        int carry = sh_carry;
        int excl = s[tid] - v;
        if (i < NN) { g_rp[i] = carry + excl; g_cur[i] = carry + excl; }
        __syncthreads();
        if (tid == 0) sh_carry = carry + s[1023];
        __syncthreads();
    }
    if (tid == 0) g_rp[NN] = sh_carry;
}

__global__ void k_fill(const int* __restrict__ src, const int* __restrict__ dst,
                       const float* __restrict__ ew) {
    int e = blockIdx.x * 256 + threadIdx.x;
    if (e < EE) {
        int s = src[e], d = dst[e];
        float w = (s == d) ? 0.0f : ew[e];
        float nw = -g_dis[s] * w * g_dis[d];
        int pos = atomicAdd(&g_cur[d], 1);
        g_col[pos] = s;
        g_val[pos] = nw;
    }
}

// ---------------- Laplacian apply (CSR gather) -------------------------------
// out[node] = sum_e val[e] * in[col[e]];  CHEB2: out = 2*that - sub[node]
template <bool CHEB2>
__global__ void k_lap(const float* __restrict__ in, float* __restrict__ out,
                      const float* __restrict__ sub) {
    int node = blockIdx.x;
    int c4 = threadIdx.x;            // float4 index within row (256 * 4 = 1024)
    int s = g_rp[node], e = g_rp[node + 1];
    float ax = 0.f, ay = 0.f, az = 0.f, aw = 0.f;
    for (int i = s; i < e; i++) {
        float w = __ldg(&g_val[i]);
        int   c = __ldg(&g_col[i]);
        float4 v = *(const float4*)(in + (size_t)c * CC + c4 * 4);
        ax += w * v.x; ay += w * v.y; az += w * v.z; aw += w * v.w;
    }
    float4 r;
    if (CHEB2) {
        float4 sb = *(const float4*)(sub + (size_t)node * CC + c4 * 4);
        r.x = 2.f * ax - sb.x; r.y = 2.f * ay - sb.y;
        r.z = 2.f * az - sb.z; r.w = 2.f * aw - sb.w;
    } else {
        r.x = ax; r.y = ay; r.z = az; r.w = aw;
    }
    *(float4*)(out + (size_t)node * CC + c4 * 4) = r;
}

// ---------------- GEMM: C[M,1024] (+)= [A0|A1|A2](M,3072) @ B(3072,1024) -----
template <bool ACCUM>
__global__ __launch_bounds__(256, 2)
void k_gemm(const float* __restrict__ A0, const float* __restrict__ A1,
            const float* __restrict__ A2, const float* __restrict__ B,
            float* __restrict__ Cm, int M) {
    const int BM = 128, BN = 128, BK = 8;
    __shared__ float As[BK][BM];
    __shared__ float Bs[BK][BN];

    int tid = threadIdx.x;
    int row0 = blockIdx.y * BM;
    int col0 = blockIdx.x * BN;
    int tx = tid & 15, ty = tid >> 4;

    int arow = tid >> 1;           // 0..127
    int aseg = (tid & 1) * 4;      // 0 or 4
    int brow = tid >> 5;           // 0..7
    int bcol = (tid & 31) * 4;     // 0..124

    float acc[8][8];
#pragma unroll
    for (int i = 0; i < 8; i++)
#pragma unroll
        for (int j = 0; j < 8; j++) acc[i][j] = 0.f;

    for (int kt = 0; kt < 3072; kt += BK) {
        const float* A = (kt < 1024) ? A0 : ((kt < 2048) ? A1 : A2);
        int kin = kt & 1023;

        int gr = row0 + arow;
        float4 av = make_float4(0.f, 0.f, 0.f, 0.f);
        if (gr < M) av = *(const float4*)(A + (size_t)gr * 1024 + kin + aseg);
        float4 bv = *(const float4*)(B + (size_t)(kt + brow) * 1024 + col0 + bcol);

        __syncthreads();
        As[aseg + 0][arow] = av.x;
        As[aseg + 1][arow] = av.y;
        As[aseg + 2][arow] = av.z;
        As[aseg + 3][arow] = av.w;
        *(float4*)&Bs[brow][bcol] = bv;
        __syncthreads();

#pragma unroll
        for (int k = 0; k < BK; k++) {
            float4 a0 = *(const float4*)&As[k][ty * 8];
            float4 a1 = *(const float4*)&As[k][ty * 8 + 4];
            float4 b0 = *(const float4*)&Bs[k][tx * 8];
            float4 b1 = *(const float4*)&Bs[k][tx * 8 + 4];
            float ra[8] = {a0.x, a0.y, a0.z, a0.w, a1.x, a1.y, a1.z, a1.w};
            float rb[8] = {b0.x, b0.y, b0.z, b0.w, b1.x, b1.y, b1.z, b1.w};
#pragma unroll
            for (int i = 0; i < 8; i++)
#pragma unroll
                for (int j = 0; j < 8; j++) acc[i][j] += ra[i] * rb[j];
        }
    }

#pragma unroll
    for (int i = 0; i < 8; i++) {
        int r = row0 + ty * 8 + i;
        if (r >= M) continue;
        float* cp = Cm + (size_t)r * 1024 + col0 + tx * 8;
#pragma unroll
        for (int sgi = 0; sgi < 2; sgi++) {
            float4 v;
            v.x = acc[i][sgi * 4 + 0]; v.y = acc[i][sgi * 4 + 1];
            v.z = acc[i][sgi * 4 + 2]; v.w = acc[i][sgi * 4 + 3];
            if (ACCUM) {
                float4 o = *(float4*)(cp + sgi * 4);
                v.x += o.x; v.y += o.y; v.z += o.z; v.w += o.w;
            }
            *(float4*)(cp + sgi * 4) = v;
        }
    }
}

// ---------------- elementwise gates ------------------------------------------
__global__ void k_gates(const float* __restrict__ H,
                        const float* __restrict__ bxz, const float* __restrict__ bhz,
                        const float* __restrict__ bxr, const float* __restrict__ bhr) {
    size_t idx = (size_t)blockIdx.x * 256 + threadIdx.x;
    if (idx < (size_t)NN * CC) {
        int c = (int)(idx & 1023);
        float z = 1.f / (1.f + expf(-(g_Zp[idx] + bxz[c] + bhz[c])));
        float r = 1.f / (1.f + expf(-(g_Rp[idx] + bxr[c] + bhr[c])));
        g_Zp[idx] = z;              // Z in place
        g_T2h[idx] = H[idx] * r;    // H * R (reusing T2h)
    }
}

__global__ void k_final(const float* __restrict__ H,
                        const float* __restrict__ bxh, const float* __restrict__ bhh,
                        float* __restrict__ out) {
    size_t idx = (size_t)blockIdx.x * 256 + threadIdx.x;
    if (idx < (size_t)NN * CC) {
        int c = (int)(idx & 1023);
        float ht = tanhf(g_Hp[idx] + bxh[c] + bhh[c]);
        float z = g_Zp[idx];
        out[idx] = z * H[idx] + (1.f - z) * ht;
    }
}

// ---------------- launch -----------------------------------------------------
extern "C" void kernel_launch(void* const* d_in, const int* in_sizes, int n_in,
                              void* d_out, int out_size) {
    const float* x   = (const float*)d_in[0];
    const float* H   = (const float*)d_in[1];
    const int*   ei  = (const int*)d_in[2];
    const int*   src = ei;
    const int*   dst = ei + EE;
    const float* ew  = (const float*)d_in[3];
    const float* Wxz = (const float*)d_in[4];
    const float* bxz = (const float*)d_in[5];
    const float* Whz = (const float*)d_in[6];
    const float* bhz = (const float*)d_in[7];
    const float* Wxr = (const float*)d_in[8];
    const float* bxr = (const float*)d_in[9];
    const float* Whr = (const float*)d_in[10];
    const float* bhr = (const float*)d_in[11];
    const float* Wxh = (const float*)d_in[12];
    const float* bxh = (const float*)d_in[13];
    const float* Whh = (const float*)d_in[14];
    const float* bhh = (const float*)d_in[15];
    float* out = (float*)d_out;

    float *T1x, *T2x, *T1h, *T2h, *Zp, *Rp, *Hp;
    cudaGetSymbolAddress((void**)&T1x, g_T1x);
    cudaGetSymbolAddress((void**)&T2x, g_T2x);
    cudaGetSymbolAddress((void**)&T1h, g_T1h);
    cudaGetSymbolAddress((void**)&T2h, g_T2h);
    cudaGetSymbolAddress((void**)&Zp,  g_Zp);
    cudaGetSymbolAddress((void**)&Rp,  g_Rp);
    cudaGetSymbolAddress((void**)&Hp,  g_Hp);

    const int NB_N = (NN + 255) / 256;     // 79
    const int NB_E = (EE + 255) / 256;     // 625
    const int NB_F = (int)(((size_t)NN * CC + 255) / 256);  // 80000

    // normalization + CSR
    k_zero<<<NB_N, 256>>>();
    k_deg <<<NB_E, 256>>>(src, dst, ew);
    k_dis <<<NB_N, 256>>>();
    k_scan<<<1, 1024>>>();
    k_fill<<<NB_E, 256>>>(src, dst, ew);

    // Chebyshev recursions for x and H
    k_lap<false><<<NN, 256>>>(x,   T1x, nullptr);
    k_lap<true> <<<NN, 256>>>(T1x, T2x, x);
    k_lap<false><<<NN, 256>>>(H,   T1h, nullptr);
    k_lap<true> <<<NN, 256>>>(T1h, T2h, H);

    dim3 gg(1024 / 128, (NN + 127) / 128);   // (8, 157)
    k_gemm<false><<<gg, 256>>>(x, T1x, T2x, Wxz, Zp, NN);
    k_gemm<true> <<<gg, 256>>>(H, T1h, T2h, Whz, Zp, NN);
    k_gemm<false><<<gg, 256>>>(x, T1x, T2x, Wxr, Rp, NN);
    k_gemm<true> <<<gg, 256>>>(H, T1h, T2h, Whr, Rp, NN);
    k_gemm<false><<<gg, 256>>>(x, T1x, T2x, Wxh, Hp, NN);

    // gates: Z (in Zp), H*R (in T2h)
    k_gates<<<NB_F, 256>>>(H, bxz, bhz, bxr, bhr);

    // Chebyshev recursion for H*R (reuse T1x/T2x as scratch)
    k_lap<false><<<NN, 256>>>(T2h, T1x, nullptr);
    k_lap<true> <<<NN, 256>>>(T1x, T2x, T2h);
    k_gemm<true><<<gg, 256>>>(T2h, T1x, T2x, Whh, Hp, NN);

    // out = Z*H + (1-Z)*tanh(Hp + bxh + bhh)
    k_final<<<NB_F, 256>>>(H, bxh, bhh, out);
}

// round 7
// speedup vs baseline: 1.9591x; 1.9591x over previous
#include <cuda_runtime.h>
#include <cuda_bf16.h>
#include <math.h>
#include <stdint.h>

#define NN 20000
#define EE 160000
#define CC 1024

// ===================== helpers ==============================================
__device__ __forceinline__ uint32_t smem_to_u32(const void* p) {
    uint32_t a;
    asm("{ .reg .u64 t; cvta.to.shared.u64 t, %1; cvt.u32.u64 %0, t; }"
        : "=r"(a) : "l"(p));
    return a;
}

__device__ __forceinline__ uint32_t SWZ(uint32_t o) {
    return o ^ ((o >> 3) & 0x70);
}

__device__ __forceinline__ void split2(float a, float b, uint32_t& hi, uint32_t& lo) {
    __nv_bfloat162 h = __floats2bfloat162_rn(a, b);
    float ra = a - __bfloat162float(h.x);
    float rb = b - __bfloat162float(h.y);
    __nv_bfloat162 l = __floats2bfloat162_rn(ra, rb);
    hi = *reinterpret_cast<uint32_t*>(&h);
    lo = *reinterpret_cast<uint32_t*>(&l);
}

__device__ __forceinline__ void ldsm4(uint32_t* r, uint32_t addr) {
    asm volatile("ldmatrix.sync.aligned.m8n8.x4.shared.b16 {%0,%1,%2,%3}, [%4];"
        : "=r"(r[0]), "=r"(r[1]), "=r"(r[2]), "=r"(r[3]) : "r"(addr));
}

__device__ __forceinline__ void mma_bf16(float* d, const uint32_t* a,
                                         const uint32_t* b) {
    asm volatile(
        "mma.sync.aligned.m16n8k16.row.col.f32.bf16.bf16.f32 "
        "{%0,%1,%2,%3},{%4,%5,%6,%7},{%8,%9},{%0,%1,%2,%3};"
        : "+f"(d[0]), "+f"(d[1]), "+f"(d[2]), "+f"(d[3])
        : "r"(a[0]), "r"(a[1]), "r"(a[2]), "r"(a[3]), "r"(b[0]), "r"(b[1]));
}

// ===================== scratch (__device__ globals) =========================
__device__ __align__(16) float g_deg[NN];
__device__ __align__(16) float g_dis[NN];
__device__ int   g_cnt[NN];
__device__ int   g_rp[NN + 1];
__device__ int   g_cur[NN];
__device__ int   g_col[EE];
__device__ __align__(16) float g_val[EE];

__device__ __align__(16) float g_T1x[(size_t)NN * CC];
__device__ __align__(16) float g_T2x[(size_t)NN * CC];
__device__ __align__(16) float g_T1h[(size_t)NN * CC];
__device__ __align__(16) float g_T2h[(size_t)NN * CC];   // later reused as H*R
__device__ __align__(16) float g_Zp[(size_t)NN * CC];
__device__ __align__(16) float g_Rp[(size_t)NN * CC];
__device__ __align__(16) float g_Hp[(size_t)NN * CC];

// ===================== graph normalization + CSR build ======================
__global__ void k_zero() {
    int i = blockIdx.x * 256 + threadIdx.x;
    if (i < NN) { g_deg[i] = 0.0f; g_cnt[i] = 0; }
}

__global__ void k_deg(const int* __restrict__ src, const int* __restrict__ dst,
                      const float* __restrict__ ew) {
    int e = blockIdx.x * 256 + threadIdx.x;
    if (e < EE) {
        int s = src[e], d = dst[e];
        float w = (s == d) ? 0.0f : ew[e];
        atomicAdd(&g_deg[s], w);
        atomicAdd(&g_cnt[d], 1);
    }
}

__global__ void k_dis() {
    int i = blockIdx.x * 256 + threadIdx.x;
    if (i < NN) {
        float d = g_deg[i];
        g_dis[i] = (d > 0.0f) ? rsqrtf(d) : 0.0f;
    }
}

__global__ void k_scan() {
    __shared__ int s[1024];
    __shared__ int sh_carry;
    int tid = threadIdx.x;
    if (tid == 0) sh_carry = 0;
    __syncthreads();
    for (int base = 0; base < NN; base += 1024) {
        int i = base + tid;
        int v = (i < NN) ? g_cnt[i] : 0;
        s[tid] = v;
        __syncthreads();
        for (int off = 1; off < 1024; off <<= 1) {
            int t = (tid >= off) ? s[tid - off] : 0;
            __syncthreads();
            s[tid] += t;
            __syncthreads();
        }
        int carry = sh_carry;
        int excl = s[tid] - v;
        if (i < NN) { g_rp[i] = carry + excl; g_cur[i] = carry + excl; }
        __syncthreads();
        if (tid == 0) sh_carry = carry + s[1023];
        __syncthreads();
    }
    if (tid == 0) g_rp[NN] = sh_carry;
}

__global__ void k_fill(const int* __restrict__ src, const int* __restrict__ dst,
                       const float* __restrict__ ew) {
    int e = blockIdx.x * 256 + threadIdx.x;
    if (e < EE) {
        int s = src[e], d = dst[e];
        float w = (s == d) ? 0.0f : ew[e];
        float nw = -g_dis[s] * w * g_dis[d];
        int pos = atomicAdd(&g_cur[d], 1);
        g_col[pos] = s;
        g_val[pos] = nw;
    }
}

// ===================== Laplacian apply (CSR gather) =========================
template <bool CHEB2>
__global__ void k_lap(const float* __restrict__ in, float* __restrict__ out,
                      const float* __restrict__ sub) {
    int node = blockIdx.x;
    int c4 = threadIdx.x;
    int s = g_rp[node], e = g_rp[node + 1];
    float ax = 0.f, ay = 0.f, az = 0.f, aw = 0.f;
    for (int i = s; i < e; i++) {
        float w = __ldg(&g_val[i]);
        int   c = __ldg(&g_col[i]);
        float4 v = *(const float4*)(in + (size_t)c * CC + c4 * 4);
        ax += w * v.x; ay += w * v.y; az += w * v.z; aw += w * v.w;
    }
    float4 r;
    if (CHEB2) {
        float4 sb = *(const float4*)(sub + (size_t)node * CC + c4 * 4);
        r.x = 2.f * ax - sb.x; r.y = 2.f * ay - sb.y;
        r.z = 2.f * az - sb.z; r.w = 2.f * aw - sb.w;
    } else {
        r.x = ax; r.y = ay; r.z = az; r.w = aw;
    }
    *(float4*)(out + (size_t)node * CC + c4 * 4) = r;
}

// ===================== MMA GEMM ============================================
// C[M,1024] (+)= sum_{seg<nseg} Aseg(M,1024) @ Wsel[(seg%3)*1024 + k][n]
// Wsel = Wa for seg 0..2, Wb for seg 3..5.
// CTA tile 128M x 128N, BK=64 bf16. fp32 emulated as Ah*Bh + Ah*Bl + Al*Bh.
// smem stage (64 KB): Ahi[128][64] 16K, Alo 16K, Bhi[128n][64k] 16K, Blo 16K
#define GEMM_SMEM 65536
#define OFF_ALO 16384u
#define OFF_BHI 32768u
#define OFF_BLO 49152u

template <bool ACCUM>
__global__ __launch_bounds__(256, 2)
void k_mmagemm(const float* __restrict__ A0, const float* __restrict__ A1,
               const float* __restrict__ A2, const float* __restrict__ A3,
               const float* __restrict__ A4, const float* __restrict__ A5,
               const float* __restrict__ Wa, const float* __restrict__ Wb,
               float* __restrict__ C, int nseg) {
    extern __shared__ __align__(1024) char sm[];
    const uint32_t smb = smem_to_u32(sm);
    const int tid = threadIdx.x;
    const int m0 = blockIdx.y * 128;
    const int n0 = blockIdx.x * 128;

    const float* As[6] = {A0, A1, A2, A3, A4, A5};
    const int nstages = nseg * 16;

    // A load mapping: 128 rows x 16 float4
    const int i4 = tid & 15, rb = tid >> 4;
    // B load mapping: 128 n x 2 k-halves of 32
    const int bn = tid & 127, bkh = tid >> 7;

    // warps: 4 m x 2 n -> warp tile 32 x 64
    const int warp = tid >> 5, lane = tid & 31;
    const int wm = (warp >> 1) * 32, wn = (warp & 1) * 64;

    float acc[2][8][4];
#pragma unroll
    for (int a = 0; a < 2; a++)
#pragma unroll
        for (int b = 0; b < 8; b++)
#pragma unroll
            for (int c = 0; c < 4; c++) acc[a][b][c] = 0.f;

    // precomputed per-lane ldmatrix address components
    const int lj = lane >> 3, lr = lane & 7;
    // A: row = base + (lj&1)*8 + lr, col = kbase + (lj>>1)*8
    const uint32_t a_row_off = (uint32_t)(((lj & 1) * 8 + lr) * 128);
    const uint32_t a_col_off = (uint32_t)((lj >> 1) * 16);   // bytes (8 bf16)
    // B: n = nb0 + (lj>>1)*8 + lr, k = kbase + (lj&1)*8
    const uint32_t b_row_off = (uint32_t)(((lj >> 1) * 8 + lr) * 128);
    const uint32_t b_col_off = (uint32_t)((lj & 1) * 16);

    for (int st = 0; st < nstages; st++) {
        const int seg = st >> 4;
        const int k0 = (st & 15) * 64;
        const float* A = As[seg];
        const float* W = (seg < 3) ? Wa : Wb;
        const int wkbase = ((seg < 3) ? seg : seg - 3) * 1024 + k0;

        __syncthreads();   // previous stage's MMA reads complete

        // ---- A tile: 128 rows x 64 fp32 -> Ahi/Alo bf16 (swizzled) ----
#pragma unroll
        for (int p = 0; p < 8; p++) {
            int r = rb + p * 16;
            float4 v = make_float4(0.f, 0.f, 0.f, 0.f);
            if (m0 + r < NN)
                v = *(const float4*)(A + (size_t)(m0 + r) * 1024 + k0 + i4 * 4);
            uint32_t h0, l0, h1, l1;
            split2(v.x, v.y, h0, l0);
            split2(v.z, v.w, h1, l1);
            uint32_t o = SWZ((uint32_t)(r * 128 + i4 * 8));
            *(uint2*)(sm + o)           = make_uint2(h0, h1);
            *(uint2*)(sm + OFF_ALO + o) = make_uint2(l0, l1);
        }

        // ---- B tile: transpose W[k][n] -> [n][k] bf16 hi/lo ----
        {
            const float* wp = W + (size_t)(wkbase + bkh * 32) * 1024 + n0 + bn;
            uint32_t rowoff = (uint32_t)(bn * 128 + bkh * 64);
#pragma unroll
            for (int p2 = 0; p2 < 16; p2++) {
                float v0 = wp[(size_t)(2 * p2) * 1024];
                float v1 = wp[(size_t)(2 * p2 + 1) * 1024];
                uint32_t h, l;
                split2(v0, v1, h, l);
                uint32_t o = SWZ(rowoff + p2 * 4);
                *(uint32_t*)(sm + OFF_BHI + o) = h;
                *(uint32_t*)(sm + OFF_BLO + o) = l;
            }
        }

        __syncthreads();

        // ---- compute: 4 k16 steps ----
#pragma unroll
        for (int kk = 0; kk < 4; kk++) {
            uint32_t kbyte = (uint32_t)(kk * 32);  // k16 -> bytes

            uint32_t ah[2][4], al[2][4];
#pragma unroll
            for (int mi = 0; mi < 2; mi++) {
                uint32_t ro = (uint32_t)((wm + mi * 16) * 128) + a_row_off;
                uint32_t ad = smb + SWZ(ro + kbyte + a_col_off);
                ldsm4(ah[mi], ad);
                ldsm4(al[mi], ad + OFF_ALO);
            }

#pragma unroll
            for (int g = 0; g < 4; g++) {
                uint32_t no = (uint32_t)((wn + g * 16) * 128) + b_row_off;
                uint32_t bd = smb + OFF_BHI + SWZ(no + kbyte + b_col_off);
                uint32_t bh[4], bl[4];
                ldsm4(bh, bd);
                ldsm4(bl, bd + 16384u);   // OFF_BLO - OFF_BHI
#pragma unroll
                for (int mi = 0; mi < 2; mi++) {
#pragma unroll
                    for (int f = 0; f < 2; f++) {
                        float* d = acc[mi][2 * g + f];
                        mma_bf16(d, ah[mi], bh + 2 * f);
                        mma_bf16(d, ah[mi], bl + 2 * f);
                        mma_bf16(d, al[mi], bh + 2 * f);
                    }
                }
            }
        }
    }

    // ---- epilogue ----
    const int gq = lane >> 2, tq = lane & 3;
#pragma unroll
    for (int mi = 0; mi < 2; mi++) {
        int r0 = m0 + wm + mi * 16 + gq;
        int r1 = r0 + 8;
#pragma unroll
        for (int nf = 0; nf < 8; nf++) {
            int col = n0 + wn + nf * 8 + tq * 2;
            float* d = acc[mi][nf];
            if (r0 < NN) {
                float* cp = C + (size_t)r0 * 1024 + col;
                float2 v = make_float2(d[0], d[1]);
                if (ACCUM) { float2 o = *(float2*)cp; v.x += o.x; v.y += o.y; }
                *(float2*)cp = v;
            }
            if (r1 < NN) {
                float* cp = C + (size_t)r1 * 1024 + col;
                float2 v = make_float2(d[2], d[3]);
                if (ACCUM) { float2 o = *(float2*)cp; v.x += o.x; v.y += o.y; }
                *(float2*)cp = v;
            }
        }
    }
}

// ===================== elementwise gates ====================================
__global__ void k_gates(const float* __restrict__ H,
                        const float* __restrict__ bxz, const float* __restrict__ bhz,
                        const float* __restrict__ bxr, const float* __restrict__ bhr) {
    size_t idx = (size_t)blockIdx.x * 256 + threadIdx.x;
    if (idx < (size_t)NN * CC) {
        int c = (int)(idx & 1023);
        float z = 1.f / (1.f + expf(-(g_Zp[idx] + bxz[c] + bhz[c])));
        float r = 1.f / (1.f + expf(-(g_Rp[idx] + bxr[c] + bhr[c])));
        g_Zp[idx] = z;
        g_T2h[idx] = H[idx] * r;    // H * R (reuse T2h)
    }
}

__global__ void k_final(const float* __restrict__ H,
                        const float* __restrict__ bxh, const float* __restrict__ bhh,
                        float* __restrict__ out) {
    size_t idx = (size_t)blockIdx.x * 256 + threadIdx.x;
    if (idx < (size_t)NN * CC) {
        int c = (int)(idx & 1023);
        float ht = tanhf(g_Hp[idx] + bxh[c] + bhh[c]);
        float z = g_Zp[idx];
        out[idx] = z * H[idx] + (1.f - z) * ht;
    }
}

// ===================== launch ===============================================
extern "C" void kernel_launch(void* const* d_in, const int* in_sizes, int n_in,
                              void* d_out, int out_size) {
    const float* x   = (const float*)d_in[0];
    const float* H   = (const float*)d_in[1];
    const int*   ei  = (const int*)d_in[2];
    const int*   src = ei;
    const int*   dst = ei + EE;
    const float* ew  = (const float*)d_in[3];
    const float* Wxz = (const float*)d_in[4];
    const float* bxz = (const float*)d_in[5];
    const float* Whz = (const float*)d_in[6];
    const float* bhz = (const float*)d_in[7];
    const float* Wxr = (const float*)d_in[8];
    const float* bxr = (const float*)d_in[9];
    const float* Whr = (const float*)d_in[10];
    const float* bhr = (const float*)d_in[11];
    const float* Wxh = (const float*)d_in[12];
    const float* bxh = (const float*)d_in[13];
    const float* Whh = (const float*)d_in[14];
    const float* bhh = (const float*)d_in[15];
    float* out = (float*)d_out;

    float *T1x, *T2x, *T1h, *T2h, *Zp, *Rp, *Hp;
    cudaGetSymbolAddress((void**)&T1x, g_T1x);
    cudaGetSymbolAddress((void**)&T2x, g_T2x);
    cudaGetSymbolAddress((void**)&T1h, g_T1h);
    cudaGetSymbolAddress((void**)&T2h, g_T2h);
    cudaGetSymbolAddress((void**)&Zp,  g_Zp);
    cudaGetSymbolAddress((void**)&Rp,  g_Rp);
    cudaGetSymbolAddress((void**)&Hp,  g_Hp);

    cudaFuncSetAttribute(k_mmagemm<false>,
        cudaFuncAttributeMaxDynamicSharedMemorySize, GEMM_SMEM);
    cudaFuncSetAttribute(k_mmagemm<true>,
        cudaFuncAttributeMaxDynamicSharedMemorySize, GEMM_SMEM);

    const int NB_N = (NN + 255) / 256;
    const int NB_E = (EE + 255) / 256;
    const int NB_F = (int)(((size_t)NN * CC + 255) / 256);

    // normalization + CSR
    k_zero<<<NB_N, 256>>>();
    k_deg <<<NB_E, 256>>>(src, dst, ew);
    k_dis <<<NB_N, 256>>>();
    k_scan<<<1, 1024>>>();
    k_fill<<<NB_E, 256>>>(src, dst, ew);

    // Chebyshev recursions for x and H
    k_lap<false><<<NN, 256>>>(x,   T1x, nullptr);
    k_lap<true> <<<NN, 256>>>(T1x, T2x, x);
    k_lap<false><<<NN, 256>>>(H,   T1h, nullptr);
    k_lap<true> <<<NN, 256>>>(T1h, T2h, H);

    dim3 gg(1024 / 128, (NN + 127) / 128);   // (8, 157)

    // Z pre-activation: x-cat @ Wxz + H-cat @ Whz  (fused, 6 segments)
    k_mmagemm<false><<<gg, 256, GEMM_SMEM>>>(x, T1x, T2x, H, T1h, T2h,
                                             Wxz, Whz, Zp, 6);
    // R pre-activation
    k_mmagemm<false><<<gg, 256, GEMM_SMEM>>>(x, T1x, T2x, H, T1h, T2h,
                                             Wxr, Whr, Rp, 6);
    // H-candidate part 1: x-cat @ Wxh
    k_mmagemm<false><<<gg, 256, GEMM_SMEM>>>(x, T1x, T2x, x, T1x, T2x,
                                             Wxh, Wxh, Hp, 3);

    // gates: Z (in Zp), H*R (in T2h)
    k_gates<<<NB_F, 256>>>(H, bxz, bhz, bxr, bhr);

    // Chebyshev recursion for H*R (reuse T1x/T2x)
    k_lap<false><<<NN, 256>>>(T2h, T1x, nullptr);
    k_lap<true> <<<NN, 256>>>(T1x, T2x, T2h);

    // H-candidate part 2: += HR-cat @ Whh
    k_mmagemm<true><<<gg, 256, GEMM_SMEM>>>(T2h, T1x, T2x, T2h, T1x, T2x,
                                            Whh, Whh, Hp, 3);

    // out = Z*H + (1-Z)*tanh(Hp + bxh + bhh)
    k_final<<<NB_F, 256>>>(H, bxh, bhh, out);
}

// round 8
// speedup vs baseline: 3.1519x; 1.6089x over previous
#include <cuda_runtime.h>
#include <cuda_bf16.h>
#include <math.h>
#include <stdint.h>

#define NN 20000
#define EE 160000
#define CC 1024

// ===================== helpers ==============================================
__device__ __forceinline__ uint32_t smem_to_u32(const void* p) {
    uint32_t a;
    asm("{ .reg .u64 t; cvta.to.shared.u64 t, %1; cvt.u32.u64 %0, t; }"
        : "=r"(a) : "l"(p));
    return a;
}

__device__ __forceinline__ uint32_t SWZ(uint32_t o) {
    return o ^ ((o >> 3) & 0x70);
}

__device__ __forceinline__ void split2(float a, float b, uint32_t& hi, uint32_t& lo) {
    __nv_bfloat162 h = __floats2bfloat162_rn(a, b);
    float ra = a - __bfloat162float(h.x);
    float rb = b - __bfloat162float(h.y);
    __nv_bfloat162 l = __floats2bfloat162_rn(ra, rb);
    hi = *reinterpret_cast<uint32_t*>(&h);
    lo = *reinterpret_cast<uint32_t*>(&l);
}

__device__ __forceinline__ void ldsm4(uint32_t* r, uint32_t addr) {
    asm volatile("ldmatrix.sync.aligned.m8n8.x4.shared.b16 {%0,%1,%2,%3}, [%4];"
        : "=r"(r[0]), "=r"(r[1]), "=r"(r[2]), "=r"(r[3]) : "r"(addr));
}

__device__ __forceinline__ void mma_bf16(float* d, const uint32_t* a,
                                         const uint32_t* b) {
    asm volatile(
        "mma.sync.aligned.m16n8k16.row.col.f32.bf16.bf16.f32 "
        "{%0,%1,%2,%3},{%4,%5,%6,%7},{%8,%9},{%0,%1,%2,%3};"
        : "+f"(d[0]), "+f"(d[1]), "+f"(d[2]), "+f"(d[3])
        : "r"(a[0]), "r"(a[1]), "r"(a[2]), "r"(a[3]), "r"(b[0]), "r"(b[1]));
}

__device__ __forceinline__ void cpa16(uint32_t dst, const void* src, bool valid) {
    asm volatile("cp.async.cg.shared.global [%0], [%1], 16, %2;"
        :: "r"(dst), "l"(src), "r"(valid ? 16 : 0));
}
#define CP_COMMIT() asm volatile("cp.async.commit_group;" ::: "memory")
#define CP_WAIT(n)  asm volatile("cp.async.wait_group %0;" :: "n"(n) : "memory")

// ===================== scratch (__device__ globals) =========================
__device__ __align__(16) float g_deg[NN];
__device__ __align__(16) float g_dis[NN];
__device__ int   g_cnt[NN];
__device__ int   g_rp[NN + 1];
__device__ int   g_cur[NN];
__device__ int   g_col[EE];
__device__ __align__(16) float g_val[EE];

__device__ __align__(16) float g_T1x[(size_t)NN * CC];
__device__ __align__(16) float g_T2x[(size_t)NN * CC];
__device__ __align__(16) float g_T1h[(size_t)NN * CC];
__device__ __align__(16) float g_T2h[(size_t)NN * CC];   // later holds H*R (fp32)
__device__ __align__(16) float g_Zp[(size_t)NN * CC];
__device__ __align__(16) float g_Rp[(size_t)NN * CC];
__device__ __align__(16) float g_Hp[(size_t)NN * CC];

// bf16 hi/lo activation buffers (x-family and H-family; H-family reused for H*R)
__device__ __align__(16) __nv_bfloat16 g_bXhi[(size_t)NN * CC];
__device__ __align__(16) __nv_bfloat16 g_bXlo[(size_t)NN * CC];
__device__ __align__(16) __nv_bfloat16 g_b1Xhi[(size_t)NN * CC];
__device__ __align__(16) __nv_bfloat16 g_b1Xlo[(size_t)NN * CC];
__device__ __align__(16) __nv_bfloat16 g_b2Xhi[(size_t)NN * CC];
__device__ __align__(16) __nv_bfloat16 g_b2Xlo[(size_t)NN * CC];
__device__ __align__(16) __nv_bfloat16 g_bHhi[(size_t)NN * CC];
__device__ __align__(16) __nv_bfloat16 g_bHlo[(size_t)NN * CC];
__device__ __align__(16) __nv_bfloat16 g_b1Hhi[(size_t)NN * CC];
__device__ __align__(16) __nv_bfloat16 g_b1Hlo[(size_t)NN * CC];
__device__ __align__(16) __nv_bfloat16 g_b2Hhi[(size_t)NN * CC];
__device__ __align__(16) __nv_bfloat16 g_b2Hlo[(size_t)NN * CC];

// transposed bf16 weights: 6 x [1024 n][3072 k]
#define WSZ ((size_t)1024 * 3072)
__device__ __align__(16) __nv_bfloat16 g_Wthi[6 * WSZ];
__device__ __align__(16) __nv_bfloat16 g_Wtlo[6 * WSZ];

// ===================== graph normalization + CSR build ======================
__global__ void k_zero() {
    int i = blockIdx.x * 256 + threadIdx.x;
    if (i < NN) { g_deg[i] = 0.0f; g_cnt[i] = 0; }
}

__global__ void k_deg(const int* __restrict__ src, const int* __restrict__ dst,
                      const float* __restrict__ ew) {
    int e = blockIdx.x * 256 + threadIdx.x;
    if (e < EE) {
        int s = src[e], d = dst[e];
        float w = (s == d) ? 0.0f : ew[e];
        atomicAdd(&g_deg[s], w);
        atomicAdd(&g_cnt[d], 1);
    }
}

__global__ void k_dis() {
    int i = blockIdx.x * 256 + threadIdx.x;
    if (i < NN) {
        float d = g_deg[i];
        g_dis[i] = (d > 0.0f) ? rsqrtf(d) : 0.0f;
    }
}

__global__ void k_scan() {
    __shared__ int s[1024];
    __shared__ int sh_carry;
    int tid = threadIdx.x;
    if (tid == 0) sh_carry = 0;
    __syncthreads();
    for (int base = 0; base < NN; base += 1024) {
        int i = base + tid;
        int v = (i < NN) ? g_cnt[i] : 0;
        s[tid] = v;
        __syncthreads();
        for (int off = 1; off < 1024; off <<= 1) {
            int t = (tid >= off) ? s[tid - off] : 0;
            __syncthreads();
            s[tid] += t;
            __syncthreads();
        }
        int carry = sh_carry;
        int excl = s[tid] - v;
        if (i < NN) { g_rp[i] = carry + excl; g_cur[i] = carry + excl; }
        __syncthreads();
        if (tid == 0) sh_carry = carry + s[1023];
        __syncthreads();
    }
    if (tid == 0) g_rp[NN] = sh_carry;
}

__global__ void k_fill(const int* __restrict__ src, const int* __restrict__ dst,
                       const float* __restrict__ ew) {
    int e = blockIdx.x * 256 + threadIdx.x;
    if (e < EE) {
        int s = src[e], d = dst[e];
        float w = (s == d) ? 0.0f : ew[e];
        float nw = -g_dis[s] * w * g_dis[d];
        int pos = atomicAdd(&g_cur[d], 1);
        g_col[pos] = s;
        g_val[pos] = nw;
    }
}

// ===================== converts =============================================
// fp32 [M][1024] -> bf16 hi/lo
__global__ void k_cvtA(const float* __restrict__ in,
                       __nv_bfloat16* __restrict__ hi,
                       __nv_bfloat16* __restrict__ lo) {
    size_t i = (size_t)blockIdx.x * 256 + threadIdx.x;   // float4 index
    if (i < (size_t)NN * CC / 4) {
        float4 v = *(const float4*)(in + i * 4);
        uint32_t h0, l0, h1, l1;
        split2(v.x, v.y, h0, l0);
        split2(v.z, v.w, h1, l1);
        *(uint2*)(hi + i * 4) = make_uint2(h0, h1);
        *(uint2*)(lo + i * 4) = make_uint2(l0, l1);
    }
}

// transpose 6 weights [3072 k][1024 n] fp32 -> [1024 n][3072 k] bf16 hi/lo
struct WPtrs { const float* w[6]; };
__global__ void k_cvtW(WPtrs wp, __nv_bfloat16* __restrict__ whi,
                       __nv_bfloat16* __restrict__ wlo) {
    __shared__ float ts[32][33];
    int kb = blockIdx.x * 32;
    int nb = blockIdx.y * 32;
    const float* W = wp.w[blockIdx.z];
    int c = threadIdx.x & 31, r8 = threadIdx.x >> 5;
#pragma unroll
    for (int i = 0; i < 4; i++) {
        int kr = r8 + i * 8;
        ts[kr][c] = W[(size_t)(kb + kr) * 1024 + nb + c];
    }
    __syncthreads();
    __nv_bfloat16* bh = whi + (size_t)blockIdx.z * WSZ;
    __nv_bfloat16* bl = wlo + (size_t)blockIdx.z * WSZ;
#pragma unroll
    for (int i = 0; i < 4; i++) {
        int nr = r8 + i * 8;
        float v = ts[c][nr];
        __nv_bfloat16 h = __float2bfloat16(v);
        __nv_bfloat16 l = __float2bfloat16(v - __bfloat162float(h));
        size_t o = (size_t)(nb + nr) * 3072 + kb + c;
        bh[o] = h;
        bl[o] = l;
    }
}

// ===================== Laplacian apply (CSR gather) + bf16 split ============
template <bool CHEB2>
__global__ void k_lap(const float* __restrict__ in, float* __restrict__ out,
                      const float* __restrict__ sub,
                      __nv_bfloat16* __restrict__ hi,
                      __nv_bfloat16* __restrict__ lo) {
    int node = blockIdx.x;
    int c4 = threadIdx.x;
    int s = g_rp[node], e = g_rp[node + 1];
    float ax = 0.f, ay = 0.f, az = 0.f, aw = 0.f;
    for (int i = s; i < e; i++) {
        float w = __ldg(&g_val[i]);
        int   c = __ldg(&g_col[i]);
        float4 v = *(const float4*)(in + (size_t)c * CC + c4 * 4);
        ax += w * v.x; ay += w * v.y; az += w * v.z; aw += w * v.w;
    }
    float4 r;
    if (CHEB2) {
        float4 sb = *(const float4*)(sub + (size_t)node * CC + c4 * 4);
        r.x = 2.f * ax - sb.x; r.y = 2.f * ay - sb.y;
        r.z = 2.f * az - sb.z; r.w = 2.f * aw - sb.w;
    } else {
        r.x = ax; r.y = ay; r.z = az; r.w = aw;
    }
    size_t o = (size_t)node * CC + c4 * 4;
    *(float4*)(out + o) = r;
    uint32_t h0, l0, h1, l1;
    split2(r.x, r.y, h0, l0);
    split2(r.z, r.w, h1, l1);
    *(uint2*)(hi + o) = make_uint2(h0, h1);
    *(uint2*)(lo + o) = make_uint2(l0, l1);
}

// ===================== pipelined MMA GEMM ===================================
// C[M,1024] (+)= sum_{seg<nseg} Aseg(M,1024) @ W(seg<3?a:b)[(seg%3)*1024+k][n]
// CTA tile 256M x 128N, BK=64 bf16. fp32-emu: Ah*Bh + Ah*Bl + Al*Bh.
// stage (96 KB): Ahi[256][64] 32K | Alo 32K | Bhi[128n][64k] 16K | Blo 16K
#define STAGE 98304u
#define GEMM_SMEM (2 * 98304)

struct SegPtrs {
    const __nv_bfloat16* hi[6];
    const __nv_bfloat16* lo[6];
};

template <bool ACCUM>
__global__ __launch_bounds__(256, 1)
void k_gemm2(SegPtrs sp,
             const __nv_bfloat16* __restrict__ Wahi, const __nv_bfloat16* __restrict__ Walo,
             const __nv_bfloat16* __restrict__ Wbhi, const __nv_bfloat16* __restrict__ Wblo,
             float* __restrict__ C, int nseg) {
    extern __shared__ __align__(1024) char sm[];
    const uint32_t smb = smem_to_u32(sm);
    const int tid = threadIdx.x;
    const int m0 = blockIdx.y * 256;
    const int n0 = blockIdx.x * 128;
    const int nst = nseg * 16;

    // warps: 4 m x 2 n -> warp tile 64 x 64
    const int warp = tid >> 5, lane = tid & 31;
    const int wm = (warp >> 1) * 64, wn = (warp & 1) * 64;
    const int lj = lane >> 3, lr = lane & 7;
    const uint32_t a_off = (uint32_t)(((lj & 1) * 8 + lr) * 128 + (lj >> 1) * 16);
    const uint32_t b_off = (uint32_t)(((lj >> 1) * 8 + lr) * 128 + (lj & 1) * 16);

    float acc[4][8][4];
#pragma unroll
    for (int a = 0; a < 4; a++)
#pragma unroll
        for (int b = 0; b < 8; b++)
#pragma unroll
            for (int c = 0; c < 4; c++) acc[a][b][c] = 0.f;

    auto issue = [&](int st) {
        const int seg = st >> 4;
        const int k0 = (st & 15) * 64;
        const int wk = (seg % 3) * 1024 + k0;
        const uint32_t buf = smb + (uint32_t)(st & 1) * STAGE;
        const __nv_bfloat16* ahi = sp.hi[seg];
        const __nv_bfloat16* alo = sp.lo[seg];
        const __nv_bfloat16* whi = (seg < 3) ? Wahi : Wbhi;
        const __nv_bfloat16* wlo = (seg < 3) ? Walo : Wblo;
#pragma unroll
        for (int t = 0; t < 8; t++) {
            int c = tid + t * 256;          // 0..2047
            int row = c >> 3, cc = c & 7;
            bool v = (m0 + row) < NN;
            size_t g = (size_t)(m0 + row) * 1024 + k0 + cc * 8;
            uint32_t o = SWZ((uint32_t)(row * 128 + cc * 16));
            cpa16(buf + o, ahi + g, v);
            cpa16(buf + 32768u + o, alo + g, v);
        }
#pragma unroll
        for (int t = 0; t < 4; t++) {
            int c = tid + t * 256;          // 0..1023
            int row = c >> 3, cc = c & 7;
            size_t g = (size_t)(n0 + row) * 3072 + wk + cc * 8;
            uint32_t o = SWZ((uint32_t)(row * 128 + cc * 16));
            cpa16(buf + 65536u + o, whi + g, true);
            cpa16(buf + 81920u + o, wlo + g, true);
        }
    };

    issue(0);
    CP_COMMIT();

    for (int st = 0; st < nst; st++) {
        if (st + 1 < nst) {
            issue(st + 1);
            CP_COMMIT();
            CP_WAIT(1);
        } else {
            CP_WAIT(0);
        }
        __syncthreads();
        const uint32_t buf = smb + (uint32_t)(st & 1) * STAGE;

#pragma unroll
        for (int kk = 0; kk < 4; kk++) {
            const uint32_t kb = (uint32_t)(kk * 32);
            uint32_t ah[4][4], al[4][4];
#pragma unroll
            for (int mi = 0; mi < 4; mi++) {
                uint32_t ad = buf + SWZ((uint32_t)((wm + mi * 16) * 128) + kb + a_off);
                ldsm4(ah[mi], ad);
                ldsm4(al[mi], ad + 32768u);
            }
#pragma unroll
            for (int g = 0; g < 4; g++) {
                uint32_t bd = buf + 65536u +
                    SWZ((uint32_t)((wn + g * 16) * 128) + kb + b_off);
                uint32_t bh[4], bl[4];
                ldsm4(bh, bd);
                ldsm4(bl, bd + 16384u);
#pragma unroll
                for (int mi = 0; mi < 4; mi++) {
#pragma unroll
                    for (int f = 0; f < 2; f++) {
                        float* d = acc[mi][2 * g + f];
                        mma_bf16(d, ah[mi], bh + 2 * f);
                        mma_bf16(d, ah[mi], bl + 2 * f);
                        mma_bf16(d, al[mi], bh + 2 * f);
                    }
                }
            }
        }
        __syncthreads();
    }

    // ---- epilogue ----
    const int gq = lane >> 2, tq = lane & 3;
#pragma unroll
    for (int mi = 0; mi < 4; mi++) {
        int r0 = m0 + wm + mi * 16 + gq;
        int r1 = r0 + 8;
#pragma unroll
        for (int nf = 0; nf < 8; nf++) {
            int col = n0 + wn + nf * 8 + tq * 2;
            float* d = acc[mi][nf];
            if (r0 < NN) {
                float* cp = C + (size_t)r0 * 1024 + col;
                float2 v = make_float2(d[0], d[1]);
                if (ACCUM) { float2 o = *(float2*)cp; v.x += o.x; v.y += o.y; }
                *(float2*)cp = v;
            }
            if (r1 < NN) {
                float* cp = C + (size_t)r1 * 1024 + col;
                float2 v = make_float2(d[2], d[3]);
                if (ACCUM) { float2 o = *(float2*)cp; v.x += o.x; v.y += o.y; }
                *(float2*)cp = v;
            }
        }
    }
}

// ===================== elementwise gates ====================================
// Z = sigmoid(Zp + bxz + bhz) -> Zp; HR = H * sigmoid(Rp + bxr + bhr)
// -> fp32 T2h and bf16 hi/lo (bHhi/bHlo)
__global__ void k_gates(const float* __restrict__ H,
                        const float* __restrict__ bxz, const float* __restrict__ bhz,
                        const float* __restrict__ bxr, const float* __restrict__ bhr) {
    size_t i = (size_t)blockIdx.x * 256 + threadIdx.x;   // float4 index
    if (i >= (size_t)NN * CC / 4) return;
    int c = (int)((i * 4) & 1023);
    float4 zp = *(const float4*)(g_Zp + i * 4);
    float4 rp = *(const float4*)(g_Rp + i * 4);
    float4 hv = *(const float4*)(H + i * 4);
    float4 bz1 = *(const float4*)(bxz + c), bz2 = *(const float4*)(bhz + c);
    float4 br1 = *(const float4*)(bxr + c), br2 = *(const float4*)(bhr + c);
    float4 z, hr;
    z.x = 1.f / (1.f + expf(-(zp.x + bz1.x + bz2.x)));
    z.y = 1.f / (1.f + expf(-(zp.y + bz1.y + bz2.y)));
    z.z = 1.f / (1.f + expf(-(zp.z + bz1.z + bz2.z)));
    z.w = 1.f / (1.f + expf(-(zp.w + bz1.w + bz2.w)));
    hr.x = hv.x / (1.f + expf(-(rp.x + br1.x + br2.x)));
    hr.y = hv.y / (1.f + expf(-(rp.y + br1.y + br2.y)));
    hr.z = hv.z / (1.f + expf(-(rp.z + br1.z + br2.z)));
    hr.w = hv.w / (1.f + expf(-(rp.w + br1.w + br2.w)));
    *(float4*)(g_Zp + i * 4) = z;
    *(float4*)(g_T2h + i * 4) = hr;
    uint32_t h0, l0, h1, l1;
    split2(hr.x, hr.y, h0, l0);
    split2(hr.z, hr.w, h1, l1);
    *(uint2*)(g_bHhi + i * 4) = make_uint2(h0, h1);
    *(uint2*)(g_bHlo + i * 4) = make_uint2(l0, l1);
}

__global__ void k_final(const float* __restrict__ H,
                        const float* __restrict__ bxh, const float* __restrict__ bhh,
                        float* __restrict__ out) {
    size_t idx = (size_t)blockIdx.x * 256 + threadIdx.x;
    if (idx < (size_t)NN * CC) {
        int c = (int)(idx & 1023);
        float ht = tanhf(g_Hp[idx] + bxh[c] + bhh[c]);
        float z = g_Zp[idx];
        out[idx] = z * H[idx] + (1.f - z) * ht;
    }
}

// ===================== launch ===============================================
extern "C" void kernel_launch(void* const* d_in, const int* in_sizes, int n_in,
                              void* d_out, int out_size) {
    const float* x   = (const float*)d_in[0];
    const float* H   = (const float*)d_in[1];
    const int*   ei  = (const int*)d_in[2];
    const int*   src = ei;
    const int*   dst = ei + EE;
    const float* ew  = (const float*)d_in[3];
    const float* Wxz = (const float*)d_in[4];
    const float* bxz = (const float*)d_in[5];
    const float* Whz = (const float*)d_in[6];
    const float* bhz = (const float*)d_in[7];
    const float* Wxr = (const float*)d_in[8];
    const float* bxr = (const float*)d_in[9];
    const float* Whr = (const float*)d_in[10];
    const float* bhr = (const float*)d_in[11];
    const float* Wxh = (const float*)d_in[12];
    const float* bxh = (const float*)d_in[13];
    const float* Whh = (const float*)d_in[14];
    const float* bhh = (const float*)d_in[15];
    float* out = (float*)d_out;

    float *T1x, *T2x, *T1h, *T2h, *Zp, *Rp, *Hp;
    cudaGetSymbolAddress((void**)&T1x, g_T1x);
    cudaGetSymbolAddress((void**)&T2x, g_T2x);
    cudaGetSymbolAddress((void**)&T1h, g_T1h);
    cudaGetSymbolAddress((void**)&T2h, g_T2h);
    cudaGetSymbolAddress((void**)&Zp,  g_Zp);
    cudaGetSymbolAddress((void**)&Rp,  g_Rp);
    cudaGetSymbolAddress((void**)&Hp,  g_Hp);

    __nv_bfloat16 *bXhi, *bXlo, *b1Xhi, *b1Xlo, *b2Xhi, *b2Xlo;
    __nv_bfloat16 *bHhi, *bHlo, *b1Hhi, *b1Hlo, *b2Hhi, *b2Hlo;
    __nv_bfloat16 *Wthi, *Wtlo;
    cudaGetSymbolAddress((void**)&bXhi,  g_bXhi);
    cudaGetSymbolAddress((void**)&bXlo,  g_bXlo);
    cudaGetSymbolAddress((void**)&b1Xhi, g_b1Xhi);
    cudaGetSymbolAddress((void**)&b1Xlo, g_b1Xlo);
    cudaGetSymbolAddress((void**)&b2Xhi, g_b2Xhi);
    cudaGetSymbolAddress((void**)&b2Xlo, g_b2Xlo);
    cudaGetSymbolAddress((void**)&bHhi,  g_bHhi);
    cudaGetSymbolAddress((void**)&bHlo,  g_bHlo);
    cudaGetSymbolAddress((void**)&b1Hhi, g_b1Hhi);
    cudaGetSymbolAddress((void**)&b1Hlo, g_b1Hlo);
    cudaGetSymbolAddress((void**)&b2Hhi, g_b2Hhi);
    cudaGetSymbolAddress((void**)&b2Hlo, g_b2Hlo);
    cudaGetSymbolAddress((void**)&Wthi,  g_Wthi);
    cudaGetSymbolAddress((void**)&Wtlo,  g_Wtlo);

    cudaFuncSetAttribute(k_gemm2<false>,
        cudaFuncAttributeMaxDynamicSharedMemorySize, GEMM_SMEM);
    cudaFuncSetAttribute(k_gemm2<true>,
        cudaFuncAttributeMaxDynamicSharedMemorySize, GEMM_SMEM);

    const int NB_N = (NN + 255) / 256;
    const int NB_E = (EE + 255) / 256;
    const int NB_F = (int)(((size_t)NN * CC + 255) / 256);
    const int NB_F4 = (int)(((size_t)NN * CC / 4 + 255) / 256);

    // normalization + CSR
    k_zero<<<NB_N, 256>>>();
    k_deg <<<NB_E, 256>>>(src, dst, ew);
    k_dis <<<NB_N, 256>>>();
    k_scan<<<1, 1024>>>();
    k_fill<<<NB_E, 256>>>(src, dst, ew);

    // weight transpose + split (order: Wxz, Whz, Wxr, Whr, Wxh, Whh)
    WPtrs wp;
    wp.w[0] = Wxz; wp.w[1] = Whz; wp.w[2] = Wxr;
    wp.w[3] = Whr; wp.w[4] = Wxh; wp.w[5] = Whh;
    k_cvtW<<<dim3(96, 32, 6), 256>>>(wp, Wthi, Wtlo);

    // x, H splits
    k_cvtA<<<NB_F4, 256>>>(x, bXhi, bXlo);
    k_cvtA<<<NB_F4, 256>>>(H, bHhi, bHlo);

    // Chebyshev recursions for x and H (+ fused bf16 splits)
    k_lap<false><<<NN, 256>>>(x,   T1x, nullptr, b1Xhi, b1Xlo);
    k_lap<true> <<<NN, 256>>>(T1x, T2x, x,       b2Xhi, b2Xlo);
    k_lap<false><<<NN, 256>>>(H,   T1h, nullptr, b1Hhi, b1Hlo);
    k_lap<true> <<<NN, 256>>>(T1h, T2h, H,       b2Hhi, b2Hlo);

    dim3 gg(1024 / 128, (NN + 255) / 256);   // (8, 79)

    SegPtrs sall;
    sall.hi[0] = bXhi;  sall.lo[0] = bXlo;
    sall.hi[1] = b1Xhi; sall.lo[1] = b1Xlo;
    sall.hi[2] = b2Xhi; sall.lo[2] = b2Xlo;
    sall.hi[3] = bHhi;  sall.lo[3] = bHlo;
    sall.hi[4] = b1Hhi; sall.lo[4] = b1Hlo;
    sall.hi[5] = b2Hhi; sall.lo[5] = b2Hlo;

    // Z pre-act: x-cat @ Wxz + H-cat @ Whz
    k_gemm2<false><<<gg, 256, GEMM_SMEM>>>(sall, Wthi, Wtlo,
        Wthi + WSZ, Wtlo + WSZ, Zp, 6);
    // R pre-act: x-cat @ Wxr + H-cat @ Whr
    k_gemm2<false><<<gg, 256, GEMM_SMEM>>>(sall, Wthi + 2 * WSZ, Wtlo + 2 * WSZ,
        Wthi + 3 * WSZ, Wtlo + 3 * WSZ, Rp, 6);
    // H-candidate part 1: x-cat @ Wxh
    k_gemm2<false><<<gg, 256, GEMM_SMEM>>>(sall, Wthi + 4 * WSZ, Wtlo + 4 * WSZ,
        Wthi + 4 * WSZ, Wtlo + 4 * WSZ, Hp, 3);

    // gates: Z -> Zp, HR -> T2h (fp32) + bHhi/bHlo (bf16)
    k_gates<<<NB_F4, 256>>>(H, bxz, bhz, bxr, bhr);

    // Chebyshev recursion for H*R (fp32 scratch T1x/T2x; bf16 into H-family)
    k_lap<false><<<NN, 256>>>(T2h, T1x, nullptr, b1Hhi, b1Hlo);
    k_lap<true> <<<NN, 256>>>(T1x, T2x, T2h,     b2Hhi, b2Hlo);

    // H-candidate part 2: += HR-cat @ Whh  (segments 3..5 slots of sall)
    SegPtrs shr;
    shr.hi[0] = bHhi;  shr.lo[0] = bHlo;
    shr.hi[1] = b1Hhi; shr.lo[1] = b1Hlo;
    shr.hi[2] = b2Hhi; shr.lo[2] = b2Hlo;
    shr.hi[3] = bHhi;  shr.lo[3] = bHlo;
    shr.hi[4] = b1Hhi; shr.lo[4] = b1Hlo;
    shr.hi[5] = b2Hhi; shr.lo[5] = b2Hlo;
    k_gemm2<true><<<gg, 256, GEMM_SMEM>>>(shr, Wthi + 5 * WSZ, Wtlo + 5 * WSZ,
        Wthi + 5 * WSZ, Wtlo + 5 * WSZ, Hp, 3);

    // out = Z*H + (1-Z)*tanh(Hp + bxh + bhh)
    k_final<<<NB_F, 256>>>(H, bxh, bhh, out);
}

// round 9
// speedup vs baseline: 4.2494x; 1.3482x over previous
#include <cuda_runtime.h>
#include <cuda_fp16.h>
#include <math.h>
#include <stdint.h>

#define NN 20000
#define EE 160000
#define CC 1024

// ===================== helpers ==============================================
__device__ __forceinline__ uint32_t smem_to_u32(const void* p) {
    uint32_t a;
    asm("{ .reg .u64 t; cvta.to.shared.u64 t, %1; cvt.u32.u64 %0, t; }"
        : "=r"(a) : "l"(p));
    return a;
}

__device__ __forceinline__ uint32_t SWZ(uint32_t o) {
    return o ^ ((o >> 3) & 0x70);
}

// fp32 pair -> fp16 hi pair + fp16 residual pair (packed half2 as u32)
__device__ __forceinline__ void splitH2(float a, float b, uint32_t& hi, uint32_t& lo) {
    __half2 h = __floats2half2_rn(a, b);
    float ra = a - __half2float(__low2half(h));
    float rb = b - __half2float(__high2half(h));
    __half2 l = __floats2half2_rn(ra, rb);
    hi = *reinterpret_cast<uint32_t*>(&h);
    lo = *reinterpret_cast<uint32_t*>(&l);
}

__device__ __forceinline__ void ldsm4(uint32_t* r, uint32_t addr) {
    asm volatile("ldmatrix.sync.aligned.m8n8.x4.shared.b16 {%0,%1,%2,%3}, [%4];"
        : "=r"(r[0]), "=r"(r[1]), "=r"(r[2]), "=r"(r[3]) : "r"(addr));
}

__device__ __forceinline__ void mma_fp16(float* d, const uint32_t* a,
                                         const uint32_t* b) {
    asm volatile(
        "mma.sync.aligned.m16n8k16.row.col.f32.f16.f16.f32 "
        "{%0,%1,%2,%3},{%4,%5,%6,%7},{%8,%9},{%0,%1,%2,%3};"
        : "+f"(d[0]), "+f"(d[1]), "+f"(d[2]), "+f"(d[3])
        : "r"(a[0]), "r"(a[1]), "r"(a[2]), "r"(a[3]), "r"(b[0]), "r"(b[1]));
}

__device__ __forceinline__ void cpa16(uint32_t dst, const void* src, bool valid) {
    asm volatile("cp.async.cg.shared.global [%0], [%1], 16, %2;"
        :: "r"(dst), "l"(src), "r"(valid ? 16 : 0));
}
#define CP_COMMIT() asm volatile("cp.async.commit_group;" ::: "memory")
#define CP_WAIT(n)  asm volatile("cp.async.wait_group %0;" :: "n"(n) : "memory")

__device__ __forceinline__ float sigm(float x) { return 1.f / (1.f + expf(-x)); }

// ===================== scratch (__device__ globals) =========================
__device__ __align__(16) float g_deg[NN];
__device__ __align__(16) float g_dis[NN];
__device__ int   g_cnt[NN];
__device__ int   g_rp[NN + 1];
__device__ int   g_cur[NN];
__device__ int   g_col[EE];
__device__ __align__(16) float g_val[EE];

__device__ __align__(16) float g_T1x[(size_t)NN * CC];
__device__ __align__(16) float g_T2x[(size_t)NN * CC];
__device__ __align__(16) float g_T1h[(size_t)NN * CC];
__device__ __align__(16) float g_T2h[(size_t)NN * CC];   // later holds H*R fp32
__device__ __align__(16) float g_Zp[(size_t)NN * CC];    // Z (post-sigmoid)
__device__ __align__(16) float g_Hp[(size_t)NN * CC];    // H-candidate pre-act

// fp16 hi/lo activation buffers: X-family, H-family, R(=H*R)-family
#define ABUF ((size_t)NN * CC)
__device__ __align__(16) __half g_hX[2 * ABUF];
__device__ __align__(16) __half g_h1X[2 * ABUF];
__device__ __align__(16) __half g_h2X[2 * ABUF];
__device__ __align__(16) __half g_hH[2 * ABUF];
__device__ __align__(16) __half g_h1H[2 * ABUF];
__device__ __align__(16) __half g_h2H[2 * ABUF];
__device__ __align__(16) __half g_hR[2 * ABUF];
__device__ __align__(16) __half g_h1R[2 * ABUF];
__device__ __align__(16) __half g_h2R[2 * ABUF];

// transposed fp16 weights: 6 x [1024 n][3072 k]
#define WSZ ((size_t)1024 * 3072)
__device__ __align__(16) __half g_Wt[6 * WSZ];

// ===================== graph normalization + CSR build ======================
__global__ void k_zero() {
    int i = blockIdx.x * 256 + threadIdx.x;
    if (i < NN) { g_deg[i] = 0.0f; g_cnt[i] = 0; }
}

__global__ void k_deg(const int* __restrict__ src, const int* __restrict__ dst,
                      const float* __restrict__ ew) {
    int e = blockIdx.x * 256 + threadIdx.x;
    if (e < EE) {
        int s = src[e], d = dst[e];
        float w = (s == d) ? 0.0f : ew[e];
        atomicAdd(&g_deg[s], w);
        atomicAdd(&g_cnt[d], 1);
    }
}

__global__ void k_dis() {
    int i = blockIdx.x * 256 + threadIdx.x;
    if (i < NN) {
        float d = g_deg[i];
        g_dis[i] = (d > 0.0f) ? rsqrtf(d) : 0.0f;
    }
}

__global__ void k_scan() {
    __shared__ int s[1024];
    __shared__ int sh_carry;
    int tid = threadIdx.x;
    if (tid == 0) sh_carry = 0;
    __syncthreads();
    for (int base = 0; base < NN; base += 1024) {
        int i = base + tid;
        int v = (i < NN) ? g_cnt[i] : 0;
        s[tid] = v;
        __syncthreads();
        for (int off = 1; off < 1024; off <<= 1) {
            int t = (tid >= off) ? s[tid - off] : 0;
            __syncthreads();
            s[tid] += t;
            __syncthreads();
        }
        int carry = sh_carry;
        int excl = s[tid] - v;
        if (i < NN) { g_rp[i] = carry + excl; g_cur[i] = carry + excl; }
        __syncthreads();
        if (tid == 0) sh_carry = carry + s[1023];
        __syncthreads();
    }
    if (tid == 0) g_rp[NN] = sh_carry;
}

__global__ void k_fill(const int* __restrict__ src, const int* __restrict__ dst,
                       const float* __restrict__ ew) {
    int e = blockIdx.x * 256 + threadIdx.x;
    if (e < EE) {
        int s = src[e], d = dst[e];
        float w = (s == d) ? 0.0f : ew[e];
        float nw = -g_dis[s] * w * g_dis[d];
        int pos = atomicAdd(&g_cur[d], 1);
        g_col[pos] = s;
        g_val[pos] = nw;
    }
}

// ===================== converts =============================================
// fp32 [M][1024] -> fp16 hi/lo
__global__ void k_cvtA(const float* __restrict__ in,
                       __half* __restrict__ hi, __half* __restrict__ lo) {
    size_t i = (size_t)blockIdx.x * 256 + threadIdx.x;   // float4 index
    if (i < (size_t)NN * CC / 4) {
        float4 v = *(const float4*)(in + i * 4);
        uint32_t h0, l0, h1, l1;
        splitH2(v.x, v.y, h0, l0);
        splitH2(v.z, v.w, h1, l1);
        *(uint2*)(hi + i * 4) = make_uint2(h0, h1);
        *(uint2*)(lo + i * 4) = make_uint2(l0, l1);
    }
}

// transpose 6 weights [3072 k][1024 n] fp32 -> [1024 n][3072 k] fp16
struct WPtrs { const float* w[6]; };
__global__ void k_cvtW(WPtrs wp, __half* __restrict__ wt) {
    __shared__ float ts[32][33];
    int kb = blockIdx.x * 32;
    int nb = blockIdx.y * 32;
    const float* W = wp.w[blockIdx.z];
    int c = threadIdx.x & 31, r8 = threadIdx.x >> 5;
#pragma unroll
    for (int i = 0; i < 4; i++) {
        int kr = r8 + i * 8;
        ts[kr][c] = W[(size_t)(kb + kr) * 1024 + nb + c];
    }
    __syncthreads();
    __half* bh = wt + (size_t)blockIdx.z * WSZ;
#pragma unroll
    for (int i = 0; i < 4; i++) {
        int nr = r8 + i * 8;
        bh[(size_t)(nb + nr) * 3072 + kb + c] = __float2half(ts[c][nr]);
    }
}

// ===================== Laplacian apply (CSR gather) + fp16 split ============
template <bool CHEB2>
__global__ void k_lap(const float* __restrict__ in, float* __restrict__ out,
                      const float* __restrict__ sub,
                      __half* __restrict__ hi, __half* __restrict__ lo) {
    int node = blockIdx.x;
    int c4 = threadIdx.x;
    int s = g_rp[node], e = g_rp[node + 1];
    float ax = 0.f, ay = 0.f, az = 0.f, aw = 0.f;
    for (int i = s; i < e; i++) {
        float w = __ldg(&g_val[i]);
        int   c = __ldg(&g_col[i]);
        float4 v = *(const float4*)(in + (size_t)c * CC + c4 * 4);
        ax += w * v.x; ay += w * v.y; az += w * v.z; aw += w * v.w;
    }
    float4 r;
    if (CHEB2) {
        float4 sb = *(const float4*)(sub + (size_t)node * CC + c4 * 4);
        r.x = 2.f * ax - sb.x; r.y = 2.f * ay - sb.y;
        r.z = 2.f * az - sb.z; r.w = 2.f * aw - sb.w;
    } else {
        r.x = ax; r.y = ay; r.z = az; r.w = aw;
    }
    size_t o = (size_t)node * CC + c4 * 4;
    *(float4*)(out + o) = r;
    uint32_t h0, l0, h1, l1;
    splitH2(r.x, r.y, h0, l0);
    splitH2(r.z, r.w, h1, l1);
    *(uint2*)(hi + o) = make_uint2(h0, h1);
    *(uint2*)(lo + o) = make_uint2(l0, l1);
}

// ===================== pipelined MMA GEMM + fused epilogues =================
// acc[M,1024] = sum_{seg<nseg} Aseg(M,1024) @ W(seg<3?a:b)[n][(seg%3)*1024+k]
// fp16 emulation: (Ah + Al) @ Wh -> 2 MMAs per k16.
// CTA tile 256M x 128N, BK=64.
// stage (80 KB): Ahi[256][64] 32K | Alo 32K | W[128n][64k] 16K
#define STAGE 81920u
#define OFF_AL 32768u
#define OFF_B  65536u
#define GEMM_SMEM (2 * 81920)

struct SegPtrsH {
    const __half* hi[6];
    const __half* lo[6];
};
struct EpiArgs {
    const float* b1; const float* b2;  // biases (EPI 1,2,3)
    const float* Hin;                  // EPI 2,3
    const float* Zin;                  // EPI 3
    __half* hr_hi; __half* hr_lo;      // EPI 2
    float* outp;                       // EPI 3
};

// EPI: 0 plain store, 1 Z=sigmoid, 2 R=sigmoid->H*R(+split), 3 final GRU mix
template <int EPI>
__global__ __launch_bounds__(256, 1)
void k_gemm3(SegPtrsH sp, const __half* __restrict__ Wa,
             const __half* __restrict__ Wb,
             float* __restrict__ C, int nseg, EpiArgs ea) {
    extern __shared__ __align__(1024) char sm[];
    const uint32_t smb = smem_to_u32(sm);
    const int tid = threadIdx.x;
    const int m0 = blockIdx.y * 256;
    const int n0 = blockIdx.x * 128;
    const int nst = nseg * 16;

    const int warp = tid >> 5, lane = tid & 31;
    const int wm = (warp >> 1) * 64, wn = (warp & 1) * 64;
    const int lj = lane >> 3, lr = lane & 7;
    const uint32_t a_off = (uint32_t)(((lj & 1) * 8 + lr) * 128 + (lj >> 1) * 16);
    const uint32_t b_off = (uint32_t)(((lj >> 1) * 8 + lr) * 128 + (lj & 1) * 16);

    float acc[4][8][4];
#pragma unroll
    for (int a = 0; a < 4; a++)
#pragma unroll
        for (int b = 0; b < 8; b++)
#pragma unroll
            for (int c = 0; c < 4; c++) acc[a][b][c] = 0.f;

    auto issue = [&](int st) {
        const int seg = st >> 4;
        const int k0 = (st & 15) * 64;
        const int wk = (seg % 3) * 1024 + k0;
        const uint32_t buf = smb + (uint32_t)(st & 1) * STAGE;
        const __half* ahi = sp.hi[seg];
        const __half* alo = sp.lo[seg];
        const __half* wt = (seg < 3) ? Wa : Wb;
#pragma unroll
        for (int t = 0; t < 8; t++) {
            int c = tid + t * 256;          // 0..2047
            int row = c >> 3, cc = c & 7;
            bool v = (m0 + row) < NN;
            size_t g = (size_t)(m0 + row) * 1024 + k0 + cc * 8;
            uint32_t o = SWZ((uint32_t)(row * 128 + cc * 16));
            cpa16(buf + o, ahi + g, v);
            cpa16(buf + OFF_AL + o, alo + g, v);
        }
#pragma unroll
        for (int t = 0; t < 4; t++) {
            int c = tid + t * 256;          // 0..1023
            int row = c >> 3, cc = c & 7;
            size_t g = (size_t)(n0 + row) * 3072 + wk + cc * 8;
            uint32_t o = SWZ((uint32_t)(row * 128 + cc * 16));
            cpa16(buf + OFF_B + o, wt + g, true);
        }
    };

    issue(0);
    CP_COMMIT();

    for (int st = 0; st < nst; st++) {
        if (st + 1 < nst) {
            issue(st + 1);
            CP_COMMIT();
            CP_WAIT(1);
        } else {
            CP_WAIT(0);
        }
        __syncthreads();
        const uint32_t buf = smb + (uint32_t)(st & 1) * STAGE;

#pragma unroll
        for (int kk = 0; kk < 4; kk++) {
            const uint32_t kb = (uint32_t)(kk * 32);
            uint32_t ah[4][4], al[4][4];
#pragma unroll
            for (int mi = 0; mi < 4; mi++) {
                uint32_t ad = buf + SWZ((uint32_t)((wm + mi * 16) * 128) + kb + a_off);
                ldsm4(ah[mi], ad);
                ldsm4(al[mi], ad + OFF_AL);
            }
#pragma unroll
            for (int g = 0; g < 4; g++) {
                uint32_t bd = buf + OFF_B +
                    SWZ((uint32_t)((wn + g * 16) * 128) + kb + b_off);
                uint32_t bh[4];
                ldsm4(bh, bd);
#pragma unroll
                for (int mi = 0; mi < 4; mi++) {
#pragma unroll
                    for (int f = 0; f < 2; f++) {
                        float* d = acc[mi][2 * g + f];
                        mma_fp16(d, ah[mi], bh + 2 * f);
                        mma_fp16(d, al[mi], bh + 2 * f);
                    }
                }
            }
        }
        __syncthreads();
    }

    // ---- fused epilogue ----
    const int gq = lane >> 2, tq = lane & 3;
#pragma unroll
    for (int mi = 0; mi < 4; mi++) {
#pragma unroll
        for (int hh = 0; hh < 2; hh++) {
            int r = m0 + wm + mi * 16 + gq + hh * 8;
            if (r >= NN) continue;
#pragma unroll
            for (int nf = 0; nf < 8; nf++) {
                int col = n0 + wn + nf * 8 + tq * 2;
                float v0 = acc[mi][nf][2 * hh];
                float v1 = acc[mi][nf][2 * hh + 1];
                size_t o = (size_t)r * 1024 + col;
                if (EPI == 0) {
                    *(float2*)(C + o) = make_float2(v0, v1);
                } else if (EPI == 1) {
                    float2 b1 = *(const float2*)(ea.b1 + col);
                    float2 b2 = *(const float2*)(ea.b2 + col);
                    float z0 = sigm(v0 + b1.x + b2.x);
                    float z1 = sigm(v1 + b1.y + b2.y);
                    *(float2*)(C + o) = make_float2(z0, z1);
                } else if (EPI == 2) {
                    float2 b1 = *(const float2*)(ea.b1 + col);
                    float2 b2 = *(const float2*)(ea.b2 + col);
                    float2 hv = *(const float2*)(ea.Hin + o);
                    float hr0 = hv.x * sigm(v0 + b1.x + b2.x);
                    float hr1 = hv.y * sigm(v1 + b1.y + b2.y);
                    *(float2*)(C + o) = make_float2(hr0, hr1);
                    uint32_t hi, lo;
                    splitH2(hr0, hr1, hi, lo);
                    *(uint32_t*)(ea.hr_hi + o) = hi;
                    *(uint32_t*)(ea.hr_lo + o) = lo;
                } else {
                    float2 b1 = *(const float2*)(ea.b1 + col);
                    float2 b2 = *(const float2*)(ea.b2 + col);
                    float2 hp = *(const float2*)(C + o);
                    float2 zv = *(const float2*)(ea.Zin + o);
                    float2 hv = *(const float2*)(ea.Hin + o);
                    float t0 = tanhf(v0 + hp.x + b1.x + b2.x);
                    float t1 = tanhf(v1 + hp.y + b1.y + b2.y);
                    float o0 = zv.x * hv.x + (1.f - zv.x) * t0;
                    float o1 = zv.y * hv.y + (1.f - zv.y) * t1;
                    *(float2*)(ea.outp + o) = make_float2(o0, o1);
                }
            }
        }
    }
}

// ===================== launch ===============================================
extern "C" void kernel_launch(void* const* d_in, const int* in_sizes, int n_in,
                              void* d_out, int out_size) {
    const float* x   = (const float*)d_in[0];
    const float* H   = (const float*)d_in[1];
    const int*   ei  = (const int*)d_in[2];
    const int*   src = ei;
    const int*   dst = ei + EE;
    const float* ew  = (const float*)d_in[3];
    const float* Wxz = (const float*)d_in[4];
    const float* bxz = (const float*)d_in[5];
    const float* Whz = (const float*)d_in[6];
    const float* bhz = (const float*)d_in[7];
    const float* Wxr = (const float*)d_in[8];
    const float* bxr = (const float*)d_in[9];
    const float* Whr = (const float*)d_in[10];
    const float* bhr = (const float*)d_in[11];
    const float* Wxh = (const float*)d_in[12];
    const float* bxh = (const float*)d_in[13];
    const float* Whh = (const float*)d_in[14];
    const float* bhh = (const float*)d_in[15];
    float* out = (float*)d_out;

    float *T1x, *T2x, *T1h, *T2h, *Zp, *Hp;
    cudaGetSymbolAddress((void**)&T1x, g_T1x);
    cudaGetSymbolAddress((void**)&T2x, g_T2x);
    cudaGetSymbolAddress((void**)&T1h, g_T1h);
    cudaGetSymbolAddress((void**)&T2h, g_T2h);
    cudaGetSymbolAddress((void**)&Zp,  g_Zp);
    cudaGetSymbolAddress((void**)&Hp,  g_Hp);

    __half *hX, *h1X, *h2X, *hH, *h1H, *h2H, *hR, *h1R, *h2R, *Wt;
    cudaGetSymbolAddress((void**)&hX,  g_hX);
    cudaGetSymbolAddress((void**)&h1X, g_h1X);
    cudaGetSymbolAddress((void**)&h2X, g_h2X);
    cudaGetSymbolAddress((void**)&hH,  g_hH);
    cudaGetSymbolAddress((void**)&h1H, g_h1H);
    cudaGetSymbolAddress((void**)&h2H, g_h2H);
    cudaGetSymbolAddress((void**)&hR,  g_hR);
    cudaGetSymbolAddress((void**)&h1R, g_h1R);
    cudaGetSymbolAddress((void**)&h2R, g_h2R);
    cudaGetSymbolAddress((void**)&Wt,  g_Wt);

    cudaFuncSetAttribute(k_gemm3<0>,
        cudaFuncAttributeMaxDynamicSharedMemorySize, GEMM_SMEM);
    cudaFuncSetAttribute(k_gemm3<1>,
        cudaFuncAttributeMaxDynamicSharedMemorySize, GEMM_SMEM);
    cudaFuncSetAttribute(k_gemm3<2>,
        cudaFuncAttributeMaxDynamicSharedMemorySize, GEMM_SMEM);
    cudaFuncSetAttribute(k_gemm3<3>,
        cudaFuncAttributeMaxDynamicSharedMemorySize, GEMM_SMEM);

    const int NB_N = (NN + 255) / 256;
    const int NB_E = (EE + 255) / 256;
    const int NB_F4 = (int)(((size_t)NN * CC / 4 + 255) / 256);

    // normalization + CSR
    k_zero<<<NB_N, 256>>>();
    k_deg <<<NB_E, 256>>>(src, dst, ew);
    k_dis <<<NB_N, 256>>>();
    k_scan<<<1, 1024>>>();
    k_fill<<<NB_E, 256>>>(src, dst, ew);

    // weight transpose + fp16 (order: Wxz, Whz, Wxr, Whr, Wxh, Whh)
    WPtrs wp;
    wp.w[0] = Wxz; wp.w[1] = Whz; wp.w[2] = Wxr;
    wp.w[3] = Whr; wp.w[4] = Wxh; wp.w[5] = Whh;
    k_cvtW<<<dim3(96, 32, 6), 256>>>(wp, Wt);

    // x, H fp16 splits
    k_cvtA<<<NB_F4, 256>>>(x, hX, hX + ABUF);
    k_cvtA<<<NB_F4, 256>>>(H, hH, hH + ABUF);

    // Chebyshev recursions for x and H (+ fused fp16 splits)
    k_lap<false><<<NN, 256>>>(x,   T1x, nullptr, h1X, h1X + ABUF);
    k_lap<true> <<<NN, 256>>>(T1x, T2x, x,       h2X, h2X + ABUF);
    k_lap<false><<<NN, 256>>>(H,   T1h, nullptr, h1H, h1H + ABUF);
    k_lap<true> <<<NN, 256>>>(T1h, T2h, H,       h2H, h2H + ABUF);

    dim3 gg(1024 / 128, (NN + 255) / 256);   // (8, 79)

    SegPtrsH sXH;
    sXH.hi[0] = hX;  sXH.lo[0] = hX + ABUF;
    sXH.hi[1] = h1X; sXH.lo[1] = h1X + ABUF;
    sXH.hi[2] = h2X; sXH.lo[2] = h2X + ABUF;
    sXH.hi[3] = hH;  sXH.lo[3] = hH + ABUF;
    sXH.hi[4] = h1H; sXH.lo[4] = h1H + ABUF;
    sXH.hi[5] = h2H; sXH.lo[5] = h2H + ABUF;

    EpiArgs ez = {}; ez.b1 = bxz; ez.b2 = bhz;
    // Z = sigmoid(Xcat@Wxz + Hcat@Whz + b) -> Zp
    k_gemm3<1><<<gg, 256, GEMM_SMEM>>>(sXH, Wt, Wt + WSZ, Zp, 6, ez);

    EpiArgs er = {}; er.b1 = bxr; er.b2 = bhr; er.Hin = H;
    er.hr_hi = hR; er.hr_lo = hR + ABUF;
    // R -> H*R: fp32 into T2h, fp16 split into hR
    k_gemm3<2><<<gg, 256, GEMM_SMEM>>>(sXH, Wt + 2 * WSZ, Wt + 3 * WSZ,
                                       T2h, 6, er);

    EpiArgs ep = {};
    // Hp = Xcat @ Wxh
    k_gemm3<0><<<gg, 256, GEMM_SMEM>>>(sXH, Wt + 4 * WSZ, Wt + 4 * WSZ,
                                       Hp, 3, ep);

    // Chebyshev recursion for H*R (fp32 scratch T1x/T2x)
    k_lap<false><<<NN, 256>>>(T2h, T1x, nullptr, h1R, h1R + ABUF);
    k_lap<true> <<<NN, 256>>>(T1x, T2x, T2h,     h2R, h2R + ABUF);

    SegPtrsH sR;
    sR.hi[0] = hR;  sR.lo[0] = hR + ABUF;
    sR.hi[1] = h1R; sR.lo[1] = h1R + ABUF;
    sR.hi[2] = h2R; sR.lo[2] = h2R + ABUF;
    sR.hi[3] = hR;  sR.lo[3] = hR + ABUF;
    sR.hi[4] = h1R; sR.lo[4] = h1R + ABUF;
    sR.hi[5] = h2R; sR.lo[5] = h2R + ABUF;

    EpiArgs ef = {}; ef.b1 = bxh; ef.b2 = bhh; ef.Hin = H; ef.Zin = Zp;
    ef.outp = out;
    // out = Z*H + (1-Z)*tanh(Hp + HRcat@Whh + b)
    k_gemm3<3><<<gg, 256, GEMM_SMEM>>>(sR, Wt + 5 * WSZ, Wt + 5 * WSZ,
                                       Hp, 3, ef);
}

// round 10
// speedup vs baseline: 6.7775x; 1.5949x over previous
#include <cuda_runtime.h>
#include <cuda_fp16.h>
#include <math.h>
#include <stdint.h>

#define NN 20000
#define EE 160000
#define CC 1024

// ===================== helpers ==============================================
__device__ __forceinline__ uint32_t smem_to_u32(const void* p) {
    uint32_t a;
    asm("{ .reg .u64 t; cvta.to.shared.u64 t, %1; cvt.u32.u64 %0, t; }"
        : "=r"(a) : "l"(p));
    return a;
}

__device__ __forceinline__ uint32_t SWZ(uint32_t o) {
    return o ^ ((o >> 3) & 0x70);
}

__device__ __forceinline__ void ldsm4(uint32_t* r, uint32_t addr) {
    asm volatile("ldmatrix.sync.aligned.m8n8.x4.shared.b16 {%0,%1,%2,%3}, [%4];"
        : "=r"(r[0]), "=r"(r[1]), "=r"(r[2]), "=r"(r[3]) : "r"(addr));
}

__device__ __forceinline__ void mma_fp16(float* d, const uint32_t* a,
                                         const uint32_t* b) {
    asm volatile(
        "mma.sync.aligned.m16n8k16.row.col.f32.f16.f16.f32 "
        "{%0,%1,%2,%3},{%4,%5,%6,%7},{%8,%9},{%0,%1,%2,%3};"
        : "+f"(d[0]), "+f"(d[1]), "+f"(d[2]), "+f"(d[3])
        : "r"(a[0]), "r"(a[1]), "r"(a[2]), "r"(a[3]), "r"(b[0]), "r"(b[1]));
}

__device__ __forceinline__ void cpa16(uint32_t dst, const void* src, bool valid) {
    asm volatile("cp.async.cg.shared.global [%0], [%1], 16, %2;"
        :: "r"(dst), "l"(src), "r"(valid ? 16 : 0));
}
#define CP_COMMIT() asm volatile("cp.async.commit_group;" ::: "memory")
#define CP_WAIT(n)  asm volatile("cp.async.wait_group %0;" :: "n"(n) : "memory")

__device__ __forceinline__ float sigm(float x) { return 1.f / (1.f + expf(-x)); }

// ===================== scratch (__device__ globals) =========================
__device__ __align__(16) float g_deg[NN];
__device__ __align__(16) float g_dis[NN];
__device__ int   g_cnt[NN];
__device__ int   g_rp[NN + 1];
__device__ int   g_cur[NN];
__device__ int   g_col[EE];
__device__ __align__(16) float g_val[EE];

__device__ __align__(16) float g_T1x[(size_t)NN * CC];
__device__ __align__(16) float g_T2x[(size_t)NN * CC];
__device__ __align__(16) float g_T1h[(size_t)NN * CC];
__device__ __align__(16) float g_T2h[(size_t)NN * CC];   // later holds H*R fp32
__device__ __align__(16) float g_Zp[(size_t)NN * CC];    // Z (post-sigmoid)
__device__ __align__(16) float g_Hp[(size_t)NN * CC];    // H-candidate pre-act

// fp16 activation buffers: X-family, H-family, R(=H*R)-family
#define ABUF ((size_t)NN * CC)
__device__ __align__(16) __half g_hX[ABUF];
__device__ __align__(16) __half g_h1X[ABUF];
__device__ __align__(16) __half g_h2X[ABUF];
__device__ __align__(16) __half g_hH[ABUF];
__device__ __align__(16) __half g_h1H[ABUF];
__device__ __align__(16) __half g_h2H[ABUF];
__device__ __align__(16) __half g_hR[ABUF];
__device__ __align__(16) __half g_h1R[ABUF];
__device__ __align__(16) __half g_h2R[ABUF];

// transposed fp16 weights: 6 x [1024 n][3072 k]
#define WSZ ((size_t)1024 * 3072)
__device__ __align__(16) __half g_Wt[6 * WSZ];

// ===================== graph normalization + CSR build ======================
__global__ void k_zero() {
    int i = blockIdx.x * 256 + threadIdx.x;
    if (i < NN) { g_deg[i] = 0.0f; g_cnt[i] = 0; }
}

__global__ void k_deg(const int* __restrict__ src, const int* __restrict__ dst,
                      const float* __restrict__ ew) {
    int e = blockIdx.x * 256 + threadIdx.x;
    if (e < EE) {
        int s = src[e], d = dst[e];
        float w = (s == d) ? 0.0f : ew[e];
        atomicAdd(&g_deg[s], w);
        atomicAdd(&g_cnt[d], 1);
    }
}

__global__ void k_dis() {
    int i = blockIdx.x * 256 + threadIdx.x;
    if (i < NN) {
        float d = g_deg[i];
        g_dis[i] = (d > 0.0f) ? rsqrtf(d) : 0.0f;
    }
}

__global__ void k_scan() {
    __shared__ int s[1024];
    __shared__ int sh_carry;
    int tid = threadIdx.x;
    if (tid == 0) sh_carry = 0;
    __syncthreads();
    for (int base = 0; base < NN; base += 1024) {
        int i = base + tid;
        int v = (i < NN) ? g_cnt[i] : 0;
        s[tid] = v;
        __syncthreads();
        for (int off = 1; off < 1024; off <<= 1) {
            int t = (tid >= off) ? s[tid - off] : 0;
            __syncthreads();
            s[tid] += t;
            __syncthreads();
        }
        int carry = sh_carry;
        int excl = s[tid] - v;
        if (i < NN) { g_rp[i] = carry + excl; g_cur[i] = carry + excl; }
        __syncthreads();
        if (tid == 0) sh_carry = carry + s[1023];
        __syncthreads();
    }
    if (tid == 0) g_rp[NN] = sh_carry;
}

__global__ void k_fill(const int* __restrict__ src, const int* __restrict__ dst,
                       const float* __restrict__ ew) {
    int e = blockIdx.x * 256 + threadIdx.x;
    if (e < EE) {
        int s = src[e], d = dst[e];
        float w = (s == d) ? 0.0f : ew[e];
        float nw = -g_dis[s] * w * g_dis[d];
        int pos = atomicAdd(&g_cur[d], 1);
        g_col[pos] = s;
        g_val[pos] = nw;
    }
}

// ===================== converts =============================================
// fp32 [M][1024] -> fp16
__global__ void k_cvtA(const float* __restrict__ in, __half* __restrict__ hi) {
    size_t i = (size_t)blockIdx.x * 256 + threadIdx.x;   // float4 index
    if (i < (size_t)NN * CC / 4) {
        float4 v = *(const float4*)(in + i * 4);
        __half2 h0 = __floats2half2_rn(v.x, v.y);
        __half2 h1 = __floats2half2_rn(v.z, v.w);
        *(uint2*)(hi + i * 4) = make_uint2(*(uint32_t*)&h0, *(uint32_t*)&h1);
    }
}

// transpose 6 weights [3072 k][1024 n] fp32 -> [1024 n][3072 k] fp16
struct WPtrs { const float* w[6]; };
__global__ void k_cvtW(WPtrs wp, __half* __restrict__ wt) {
    __shared__ float ts[32][33];
    int kb = blockIdx.x * 32;
    int nb = blockIdx.y * 32;
    const float* W = wp.w[blockIdx.z];
    int c = threadIdx.x & 31, r8 = threadIdx.x >> 5;
#pragma unroll
    for (int i = 0; i < 4; i++) {
        int kr = r8 + i * 8;
        ts[kr][c] = W[(size_t)(kb + kr) * 1024 + nb + c];
    }
    __syncthreads();
    __half* bh = wt + (size_t)blockIdx.z * WSZ;
#pragma unroll
    for (int i = 0; i < 4; i++) {
        int nr = r8 + i * 8;
        bh[(size_t)(nb + nr) * 3072 + kb + c] = __float2half(ts[c][nr]);
    }
}

// ===================== Laplacian apply (CSR gather) + fp16 cvt ==============
template <bool CHEB2>
__global__ void k_lap(const float* __restrict__ in, float* __restrict__ out,
                      const float* __restrict__ sub, __half* __restrict__ hi) {
    int node = blockIdx.x;
    int c4 = threadIdx.x;
    int s = g_rp[node], e = g_rp[node + 1];
    float ax = 0.f, ay = 0.f, az = 0.f, aw = 0.f;
    for (int i = s; i < e; i++) {
        float w = __ldg(&g_val[i]);
        int   c = __ldg(&g_col[i]);
        float4 v = *(const float4*)(in + (size_t)c * CC + c4 * 4);
        ax += w * v.x; ay += w * v.y; az += w * v.z; aw += w * v.w;
    }
    float4 r;
    if (CHEB2) {
        float4 sb = *(const float4*)(sub + (size_t)node * CC + c4 * 4);
        r.x = 2.f * ax - sb.x; r.y = 2.f * ay - sb.y;
        r.z = 2.f * az - sb.z; r.w = 2.f * aw - sb.w;
    } else {
        r.x = ax; r.y = ay; r.z = az; r.w = aw;
    }
    size_t o = (size_t)node * CC + c4 * 4;
    *(float4*)(out + o) = r;
    __half2 h0 = __floats2half2_rn(r.x, r.y);
    __half2 h1 = __floats2half2_rn(r.z, r.w);
    *(uint2*)(hi + o) = make_uint2(*(uint32_t*)&h0, *(uint32_t*)&h1);
}

// ===================== pipelined MMA GEMM + fused epilogues =================
// acc[M,1024] = sum_{seg<nseg} Aseg(M,1024) @ W(seg<3?a:b)[n][(seg%3)*1024+k]
// pure fp16 inputs, fp32 accum: 1 MMA per k16 pair.
// CTA tile 256M x 128N, BK=64, 3-stage cp.async pipeline.
// stage (48 KB): A[256][64] 32K | W[128n][64k] 16K
#define STAGE 49152u
#define OFF_B  32768u
#define GEMM_SMEM (3 * 49152)

struct SegPtrsH { const __half* a[6]; };
struct EpiArgs {
    const float* b1; const float* b2;  // biases (EPI 1,2,3)
    const float* Hin;                  // EPI 2,3
    const float* Zin;                  // EPI 3
    __half* hr_hi;                     // EPI 2
    float* outp;                       // EPI 3
};

// EPI: 0 plain store, 1 Z=sigmoid, 2 R=sigmoid->H*R(+fp16), 3 final GRU mix
template <int EPI>
__global__ __launch_bounds__(256, 1)
void k_gemm3(SegPtrsH sp, const __half* __restrict__ Wa,
             const __half* __restrict__ Wb,
             float* __restrict__ C, int nseg, EpiArgs ea) {
    extern __shared__ __align__(1024) char sm[];
    const uint32_t smb = smem_to_u32(sm);
    const int tid = threadIdx.x;
    const int m0 = blockIdx.y * 256;
    const int n0 = blockIdx.x * 128;
    const int nst = nseg * 16;

    const int warp = tid >> 5, lane = tid & 31;
    const int wm = (warp >> 1) * 64, wn = (warp & 1) * 64;
    const int lj = lane >> 3, lr = lane & 7;
    const uint32_t a_off = (uint32_t)(((lj & 1) * 8 + lr) * 128 + (lj >> 1) * 16);
    const uint32_t b_off = (uint32_t)(((lj >> 1) * 8 + lr) * 128 + (lj & 1) * 16);

    float acc[4][8][4];
#pragma unroll
    for (int a = 0; a < 4; a++)
#pragma unroll
        for (int b = 0; b < 8; b++)
#pragma unroll
            for (int c = 0; c < 4; c++) acc[a][b][c] = 0.f;

    auto issue = [&](int st) {
        const int seg = st >> 4;
        const int k0 = (st & 15) * 64;
        const int wk = (seg % 3) * 1024 + k0;
        const uint32_t buf = smb + (uint32_t)(st % 3) * STAGE;
        const __half* ah = sp.a[seg];
        const __half* wt = (seg < 3) ? Wa : Wb;
#pragma unroll
        for (int t = 0; t < 8; t++) {
            int c = tid + t * 256;          // 0..2047
            int row = c >> 3, cc = c & 7;
            bool v = (m0 + row) < NN;
            size_t g = (size_t)(m0 + row) * 1024 + k0 + cc * 8;
            cpa16(buf + SWZ((uint32_t)(row * 128 + cc * 16)), ah + g, v);
        }
#pragma unroll
        for (int t = 0; t < 4; t++) {
            int c = tid + t * 256;          // 0..1023
            int row = c >> 3, cc = c & 7;
            size_t g = (size_t)(n0 + row) * 3072 + wk + cc * 8;
            cpa16(buf + OFF_B + SWZ((uint32_t)(row * 128 + cc * 16)), wt + g, true);
        }
    };

    issue(0);
    CP_COMMIT();
    if (nst > 1) { issue(1); CP_COMMIT(); }

    for (int st = 0; st < nst; st++) {
        if (st + 2 < nst) {
            issue(st + 2);
            CP_COMMIT();
            CP_WAIT(2);
        } else if (st + 1 < nst) {
            CP_WAIT(1);
        } else {
            CP_WAIT(0);
        }
        __syncthreads();
        const uint32_t buf = smb + (uint32_t)(st % 3) * STAGE;

#pragma unroll
        for (int kk = 0; kk < 4; kk++) {
            const uint32_t kb = (uint32_t)(kk * 32);
            uint32_t ah[4][4];
#pragma unroll
            for (int mi = 0; mi < 4; mi++) {
                uint32_t ad = buf + SWZ((uint32_t)((wm + mi * 16) * 128) + kb + a_off);
                ldsm4(ah[mi], ad);
            }
#pragma unroll
            for (int g = 0; g < 4; g++) {
                uint32_t bd = buf + OFF_B +
                    SWZ((uint32_t)((wn + g * 16) * 128) + kb + b_off);
                uint32_t bh[4];
                ldsm4(bh, bd);
#pragma unroll
                for (int mi = 0; mi < 4; mi++) {
#pragma unroll
                    for (int f = 0; f < 2; f++)
                        mma_fp16(acc[mi][2 * g + f], ah[mi], bh + 2 * f);
                }
            }
        }
        __syncthreads();
    }

    // ---- fused epilogue ----
    const int gq = lane >> 2, tq = lane & 3;
#pragma unroll
    for (int mi = 0; mi < 4; mi++) {
#pragma unroll
        for (int hh = 0; hh < 2; hh++) {
            int r = m0 + wm + mi * 16 + gq + hh * 8;
            if (r >= NN) continue;
#pragma unroll
            for (int nf = 0; nf < 8; nf++) {
                int col = n0 + wn + nf * 8 + tq * 2;
                float v0 = acc[mi][nf][2 * hh];
                float v1 = acc[mi][nf][2 * hh + 1];
                size_t o = (size_t)r * 1024 + col;
                if (EPI == 0) {
                    *(float2*)(C + o) = make_float2(v0, v1);
                } else if (EPI == 1) {
                    float2 b1 = *(const float2*)(ea.b1 + col);
                    float2 b2 = *(const float2*)(ea.b2 + col);
                    float z0 = sigm(v0 + b1.x + b2.x);
                    float z1 = sigm(v1 + b1.y + b2.y);
                    *(float2*)(C + o) = make_float2(z0, z1);
                } else if (EPI == 2) {
                    float2 b1 = *(const float2*)(ea.b1 + col);
                    float2 b2 = *(const float2*)(ea.b2 + col);
                    float2 hv = *(const float2*)(ea.Hin + o);
                    float hr0 = hv.x * sigm(v0 + b1.x + b2.x);
                    float hr1 = hv.y * sigm(v1 + b1.y + b2.y);
                    *(float2*)(C + o) = make_float2(hr0, hr1);
                    __half2 h = __floats2half2_rn(hr0, hr1);
                    *(uint32_t*)(ea.hr_hi + o) = *(uint32_t*)&h;
                } else {
                    float2 b1 = *(const float2*)(ea.b1 + col);
                    float2 b2 = *(const float2*)(ea.b2 + col);
                    float2 hp = *(const float2*)(C + o);
                    float2 zv = *(const float2*)(ea.Zin + o);
                    float2 hv = *(const float2*)(ea.Hin + o);
                    float t0 = tanhf(v0 + hp.x + b1.x + b2.x);
                    float t1 = tanhf(v1 + hp.y + b1.y + b2.y);
                    float o0 = zv.x * hv.x + (1.f - zv.x) * t0;
                    float o1 = zv.y * hv.y + (1.f - zv.y) * t1;
                    *(float2*)(ea.outp + o) = make_float2(o0, o1);
                }
            }
        }
    }
}

// ===================== launch ===============================================
extern "C" void kernel_launch(void* const* d_in, const int* in_sizes, int n_in,
                              void* d_out, int out_size) {
    const float* x   = (const float*)d_in[0];
    const float* H   = (const float*)d_in[1];
    const int*   ei  = (const int*)d_in[2];
    const int*   src = ei;
    const int*   dst = ei + EE;
    const float* ew  = (const float*)d_in[3];
    const float* Wxz = (const float*)d_in[4];
    const float* bxz = (const float*)d_in[5];
    const float* Whz = (const float*)d_in[6];
    const float* bhz = (const float*)d_in[7];
    const float* Wxr = (const float*)d_in[8];
    const float* bxr = (const float*)d_in[9];
    const float* Whr = (const float*)d_in[10];
    const float* bhr = (const float*)d_in[11];
    const float* Wxh = (const float*)d_in[12];
    const float* bxh = (const float*)d_in[13];
    const float* Whh = (const float*)d_in[14];
    const float* bhh = (const float*)d_in[15];
    float* out = (float*)d_out;

    float *T1x, *T2x, *T1h, *T2h, *Zp, *Hp;
    cudaGetSymbolAddress((void**)&T1x, g_T1x);
    cudaGetSymbolAddress((void**)&T2x, g_T2x);
    cudaGetSymbolAddress((void**)&T1h, g_T1h);
    cudaGetSymbolAddress((void**)&T2h, g_T2h);
    cudaGetSymbolAddress((void**)&Zp,  g_Zp);
    cudaGetSymbolAddress((void**)&Hp,  g_Hp);

    __half *hX, *h1X, *h2X, *hH, *h1H, *h2H, *hR, *h1R, *h2R, *Wt;
    cudaGetSymbolAddress((void**)&hX,  g_hX);
    cudaGetSymbolAddress((void**)&h1X, g_h1X);
    cudaGetSymbolAddress((void**)&h2X, g_h2X);
    cudaGetSymbolAddress((void**)&hH,  g_hH);
    cudaGetSymbolAddress((void**)&h1H, g_h1H);
    cudaGetSymbolAddress((void**)&h2H, g_h2H);
    cudaGetSymbolAddress((void**)&hR,  g_hR);
    cudaGetSymbolAddress((void**)&h1R, g_h1R);
    cudaGetSymbolAddress((void**)&h2R, g_h2R);
    cudaGetSymbolAddress((void**)&Wt,  g_Wt);

    cudaFuncSetAttribute(k_gemm3<0>,
        cudaFuncAttributeMaxDynamicSharedMemorySize, GEMM_SMEM);
    cudaFuncSetAttribute(k_gemm3<1>,
        cudaFuncAttributeMaxDynamicSharedMemorySize, GEMM_SMEM);
    cudaFuncSetAttribute(k_gemm3<2>,
        cudaFuncAttributeMaxDynamicSharedMemorySize, GEMM_SMEM);
    cudaFuncSetAttribute(k_gemm3<3>,
        cudaFuncAttributeMaxDynamicSharedMemorySize, GEMM_SMEM);

    const int NB_N = (NN + 255) / 256;
    const int NB_E = (EE + 255) / 256;
    const int NB_F4 = (int)(((size_t)NN * CC / 4 + 255) / 256);

    // normalization + CSR
    k_zero<<<NB_N, 256>>>();
    k_deg <<<NB_E, 256>>>(src, dst, ew);
    k_dis <<<NB_N, 256>>>();
    k_scan<<<1, 1024>>>();
    k_fill<<<NB_E, 256>>>(src, dst, ew);

    // weight transpose + fp16 (order: Wxz, Whz, Wxr, Whr, Wxh, Whh)
    WPtrs wp;
    wp.w[0] = Wxz; wp.w[1] = Whz; wp.w[2] = Wxr;
    wp.w[3] = Whr; wp.w[4] = Wxh; wp.w[5] = Whh;
    k_cvtW<<<dim3(96, 32, 6), 256>>>(wp, Wt);

    // x, H fp16 converts
    k_cvtA<<<NB_F4, 256>>>(x, hX);
    k_cvtA<<<NB_F4, 256>>>(H, hH);

    // Chebyshev recursions for x and H (+ fused fp16 converts)
    k_lap<false><<<NN, 256>>>(x,   T1x, nullptr, h1X);
    k_lap<true> <<<NN, 256>>>(T1x, T2x, x,       h2X);
    k_lap<false><<<NN, 256>>>(H,   T1h, nullptr, h1H);
    k_lap<true> <<<NN, 256>>>(T1h, T2h, H,       h2H);

    dim3 gg(1024 / 128, (NN + 255) / 256);   // (8, 79)

    SegPtrsH sXH;
    sXH.a[0] = hX;  sXH.a[1] = h1X; sXH.a[2] = h2X;
    sXH.a[3] = hH;  sXH.a[4] = h1H; sXH.a[5] = h2H;

    EpiArgs ez = {}; ez.b1 = bxz; ez.b2 = bhz;
    // Z = sigmoid(Xcat@Wxz + Hcat@Whz + b) -> Zp
    k_gemm3<1><<<gg, 256, GEMM_SMEM>>>(sXH, Wt, Wt + WSZ, Zp, 6, ez);

    EpiArgs er = {}; er.b1 = bxr; er.b2 = bhr; er.Hin = H; er.hr_hi = hR;
    // R -> H*R: fp32 into T2h, fp16 into hR
    k_gemm3<2><<<gg, 256, GEMM_SMEM>>>(sXH, Wt + 2 * WSZ, Wt + 3 * WSZ,
                                       T2h, 6, er);

    EpiArgs ep = {};
    // Hp = Xcat @ Wxh
    k_gemm3<0><<<gg, 256, GEMM_SMEM>>>(sXH, Wt + 4 * WSZ, Wt + 4 * WSZ,
                                       Hp, 3, ep);

    // Chebyshev recursion for H*R (fp32 scratch T1x/T2x)
    k_lap<false><<<NN, 256>>>(T2h, T1x, nullptr, h1R);
    k_lap<true> <<<NN, 256>>>(T1x, T2x, T2h,     h2R);

    SegPtrsH sR;
    sR.a[0] = hR;  sR.a[1] = h1R; sR.a[2] = h2R;
    sR.a[3] = hR;  sR.a[4] = h1R; sR.a[5] = h2R;

    EpiArgs ef = {}; ef.b1 = bxh; ef.b2 = bhh; ef.Hin = H; ef.Zin = Zp;
    ef.outp = out;
    // out = Z*H + (1-Z)*tanh(Hp + HRcat@Whh + b)
    k_gemm3<3><<<gg, 256, GEMM_SMEM>>>(sR, Wt + 5 * WSZ, Wt + 5 * WSZ,
                                       Hp, 3, ef);
}

// round 11
// speedup vs baseline: 7.2127x; 1.0642x over previous
#include <cuda_runtime.h>
#include <cuda_fp16.h>
#include <math.h>
#include <stdint.h>

#define NN 20000
#define EE 160000
#define CC 1024

// ===================== helpers ==============================================
__device__ __forceinline__ uint32_t smem_to_u32(const void* p) {
    uint32_t a;
    asm("{ .reg .u64 t; cvta.to.shared.u64 t, %1; cvt.u32.u64 %0, t; }"
        : "=r"(a) : "l"(p));
    return a;
}

__device__ __forceinline__ uint32_t SWZ(uint32_t o) {
    return o ^ ((o >> 3) & 0x70);
}

__device__ __forceinline__ void ldsm4(uint32_t* r, uint32_t addr) {
    asm volatile("ldmatrix.sync.aligned.m8n8.x4.shared.b16 {%0,%1,%2,%3}, [%4];"
        : "=r"(r[0]), "=r"(r[1]), "=r"(r[2]), "=r"(r[3]) : "r"(addr));
}

__device__ __forceinline__ void mma_fp16(float* d, const uint32_t* a,
                                         const uint32_t* b) {
    asm volatile(
        "mma.sync.aligned.m16n8k16.row.col.f32.f16.f16.f32 "
        "{%0,%1,%2,%3},{%4,%5,%6,%7},{%8,%9},{%0,%1,%2,%3};"
        : "+f"(d[0]), "+f"(d[1]), "+f"(d[2]), "+f"(d[3])
        : "r"(a[0]), "r"(a[1]), "r"(a[2]), "r"(a[3]), "r"(b[0]), "r"(b[1]));
}

__device__ __forceinline__ void cpa16(uint32_t dst, const void* src, bool valid) {
    asm volatile("cp.async.cg.shared.global [%0], [%1], 16, %2;"
        :: "r"(dst), "l"(src), "r"(valid ? 16 : 0));
}
#define CP_COMMIT() asm volatile("cp.async.commit_group;" ::: "memory")
#define CP_WAIT(n)  asm volatile("cp.async.wait_group %0;" :: "n"(n) : "memory")

__device__ __forceinline__ float sigm(float x) { return 1.f / (1.f + expf(-x)); }

// ===================== scratch (__device__ globals) =========================
__device__ __align__(16) float g_deg[NN];
__device__ __align__(16) float g_dis[NN];
__device__ int   g_cnt[NN];
__device__ int   g_rp[NN + 1];
__device__ int   g_cur[NN];
__device__ int   g_col[EE];
__device__ __align__(16) float g_val[EE];

__device__ __align__(16) float g_T2h[(size_t)NN * CC];   // H*R fp32 (sub term)
__device__ __align__(16) float g_Zp[(size_t)NN * CC];    // Z (post-sigmoid)
__device__ __align__(16) float g_Hp[(size_t)NN * CC];    // H-candidate pre-act

// fp16 activation buffers: X-family, H-family, R(=H*R)-family
#define ABUF ((size_t)NN * CC)
__device__ __align__(16) __half g_hX[ABUF];
__device__ __align__(16) __half g_h1X[ABUF];
__device__ __align__(16) __half g_h2X[ABUF];
__device__ __align__(16) __half g_hH[ABUF];
__device__ __align__(16) __half g_h1H[ABUF];
__device__ __align__(16) __half g_h2H[ABUF];
__device__ __align__(16) __half g_hR[ABUF];
__device__ __align__(16) __half g_h1R[ABUF];
__device__ __align__(16) __half g_h2R[ABUF];

// transposed fp16 weights: 6 x [1024 n][3072 k]
#define WSZ ((size_t)1024 * 3072)
__device__ __align__(16) __half g_Wt[6 * WSZ];

// ===================== graph normalization + CSR build ======================
__global__ void k_zero() {
    int i = blockIdx.x * 256 + threadIdx.x;
    if (i < NN) { g_deg[i] = 0.0f; g_cnt[i] = 0; }
}

__global__ void k_deg(const int* __restrict__ src, const int* __restrict__ dst,
                      const float* __restrict__ ew) {
    int e = blockIdx.x * 256 + threadIdx.x;
    if (e < EE) {
        int s = src[e], d = dst[e];
        float w = (s == d) ? 0.0f : ew[e];
        atomicAdd(&g_deg[s], w);
        atomicAdd(&g_cnt[d], 1);
    }
}

__global__ void k_dis() {
    int i = blockIdx.x * 256 + threadIdx.x;
    if (i < NN) {
        float d = g_deg[i];
        g_dis[i] = (d > 0.0f) ? rsqrtf(d) : 0.0f;
    }
}

// exclusive scan of g_cnt -> g_rp / g_cur; warp-shuffle based, 1 block x 1024
__global__ void k_scan() {
    __shared__ int wsum[32];
    __shared__ int sh_carry;
    int tid = threadIdx.x;
    int lane = tid & 31, wid = tid >> 5;
    if (tid == 0) sh_carry = 0;
    __syncthreads();
    for (int base = 0; base < NN; base += 1024) {
        int i = base + tid;
        int v = (i < NN) ? g_cnt[i] : 0;
        // warp inclusive scan
        int inc = v;
#pragma unroll
        for (int off = 1; off < 32; off <<= 1) {
            int t = __shfl_up_sync(0xFFFFFFFFu, inc, off);
            if (lane >= off) inc += t;
        }
        if (lane == 31) wsum[wid] = inc;
        __syncthreads();
        if (wid == 0) {
            int wv = wsum[lane];
            int winc = wv;
#pragma unroll
            for (int off = 1; off < 32; off <<= 1) {
                int t = __shfl_up_sync(0xFFFFFFFFu, winc, off);
                if (lane >= off) winc += t;
            }
            wsum[lane] = winc - wv;   // exclusive warp offsets
        }
        __syncthreads();
        int excl = sh_carry + wsum[wid] + inc - v;
        if (i < NN) { g_rp[i] = excl; g_cur[i] = excl; }
        __syncthreads();
        if (tid == 1023) sh_carry = excl + v;
        __syncthreads();
    }
    if (tid == 0) g_rp[NN] = sh_carry;
}

__global__ void k_fill(const int* __restrict__ src, const int* __restrict__ dst,
                       const float* __restrict__ ew) {
    int e = blockIdx.x * 256 + threadIdx.x;
    if (e < EE) {
        int s = src[e], d = dst[e];
        float w = (s == d) ? 0.0f : ew[e];
        float nw = -g_dis[s] * w * g_dis[d];
        int pos = atomicAdd(&g_cur[d], 1);
        g_col[pos] = s;
        g_val[pos] = nw;
    }
}

// ===================== converts =============================================
// fp32 [M][1024] -> fp16
__global__ void k_cvtA(const float* __restrict__ in, __half* __restrict__ hi) {
    size_t i = (size_t)blockIdx.x * 256 + threadIdx.x;   // float4 index
    if (i < (size_t)NN * CC / 4) {
        float4 v = *(const float4*)(in + i * 4);
        __half2 h0 = __floats2half2_rn(v.x, v.y);
        __half2 h1 = __floats2half2_rn(v.z, v.w);
        *(uint2*)(hi + i * 4) = make_uint2(*(uint32_t*)&h0, *(uint32_t*)&h1);
    }
}

// transpose 6 weights [3072 k][1024 n] fp32 -> [1024 n][3072 k] fp16
struct WPtrs { const float* w[6]; };
__global__ void k_cvtW(WPtrs wp, __half* __restrict__ wt) {
    __shared__ float ts[32][33];
    int kb = blockIdx.x * 32;
    int nb = blockIdx.y * 32;
    const float* W = wp.w[blockIdx.z];
    int c = threadIdx.x & 31, r8 = threadIdx.x >> 5;
#pragma unroll
    for (int i = 0; i < 4; i++) {
        int kr = r8 + i * 8;
        ts[kr][c] = W[(size_t)(kb + kr) * 1024 + nb + c];
    }
    __syncthreads();
    __half* bh = wt + (size_t)blockIdx.z * WSZ;
#pragma unroll
    for (int i = 0; i < 4; i++) {
        int nr = r8 + i * 8;
        bh[(size_t)(nb + nr) * 3072 + kb + c] = __float2half(ts[c][nr]);
    }
}

// ============ Laplacian apply: fp16 gather, fp32 accum, fp16 out ============
// out[node] = sum val*in[col]  (CHEB2: 2*that - sub[node])
template <bool CHEB2>
__global__ void k_lap16(const __half* __restrict__ in,
                        const float* __restrict__ sub,
                        __half* __restrict__ out) {
    int node = blockIdx.x;
    int c4 = threadIdx.x;                     // 4 halves per thread
    int s = g_rp[node], e = g_rp[node + 1];
    float a0 = 0.f, a1 = 0.f, a2 = 0.f, a3 = 0.f;
    for (int i = s; i < e; i++) {
        float w = __ldg(&g_val[i]);
        int   c = __ldg(&g_col[i]);
        uint2 hv = *(const uint2*)(in + (size_t)c * CC + c4 * 4);
        __half2 p0 = *reinterpret_cast<__half2*>(&hv.x);
        __half2 p1 = *reinterpret_cast<__half2*>(&hv.y);
        float2 f0 = __half22float2(p0);
        float2 f1 = __half22float2(p1);
        a0 += w * f0.x; a1 += w * f0.y; a2 += w * f1.x; a3 += w * f1.y;
    }
    if (CHEB2) {
        float4 sb = *(const float4*)(sub + (size_t)node * CC + c4 * 4);
        a0 = 2.f * a0 - sb.x; a1 = 2.f * a1 - sb.y;
        a2 = 2.f * a2 - sb.z; a3 = 2.f * a3 - sb.w;
    }
    __half2 o0 = __floats2half2_rn(a0, a1);
    __half2 o1 = __floats2half2_rn(a2, a3);
    *(uint2*)(out + (size_t)node * CC + c4 * 4) =
        make_uint2(*(uint32_t*)&o0, *(uint32_t*)&o1);
}

// ===================== pipelined MMA GEMM + fused epilogues =================
// acc[M,1024] = sum_{seg<nseg} Aseg(M,1024) @ W(seg<3?a:b)[n][(seg%3)*1024+k]
// pure fp16 inputs, fp32 accum: 1 MMA per k16 pair.
// CTA tile 256M x 128N, BK=64, 3-stage cp.async pipeline.
// stage (48 KB): A[256][64] 32K | W[128n][64k] 16K
#define STAGE 49152u
#define OFF_B  32768u
#define GEMM_SMEM (3 * 49152)

struct SegPtrsH { const __half* a[6]; };
struct EpiArgs {
    const float* b1; const float* b2;  // biases (EPI 1,2,3)
    const float* Hin;                  // EPI 2,3
    const float* Zin;                  // EPI 3
    __half* hr_hi;                     // EPI 2
    float* hr_f32;                     // EPI 2
    float* outp;                       // EPI 3
};

// EPI: 0 plain store, 1 Z=sigmoid, 2 R=sigmoid->H*R(fp32+fp16), 3 final mix
template <int EPI>
__global__ __launch_bounds__(256, 1)
void k_gemm3(SegPtrsH sp, const __half* __restrict__ Wa,
             const __half* __restrict__ Wb,
             float* __restrict__ C, int nseg, EpiArgs ea) {
    extern __shared__ __align__(1024) char sm[];
    const uint32_t smb = smem_to_u32(sm);
    const int tid = threadIdx.x;
    const int m0 = blockIdx.y * 256;
    const int n0 = blockIdx.x * 128;
    const int nst = nseg * 16;

    const int warp = tid >> 5, lane = tid & 31;
    const int wm = (warp >> 1) * 64, wn = (warp & 1) * 64;
    const int lj = lane >> 3, lr = lane & 7;
    const uint32_t a_off = (uint32_t)(((lj & 1) * 8 + lr) * 128 + (lj >> 1) * 16);
    const uint32_t b_off = (uint32_t)(((lj >> 1) * 8 + lr) * 128 + (lj & 1) * 16);

    float acc[4][8][4];
#pragma unroll
    for (int a = 0; a < 4; a++)
#pragma unroll
        for (int b = 0; b < 8; b++)
#pragma unroll
            for (int c = 0; c < 4; c++) acc[a][b][c] = 0.f;

    auto issue = [&](int st) {
        const int seg = st >> 4;
        const int k0 = (st & 15) * 64;
        const int wk = (seg % 3) * 1024 + k0;
        const uint32_t buf = smb + (uint32_t)(st % 3) * STAGE;
        const __half* ah = sp.a[seg];
        const __half* wt = (seg < 3) ? Wa : Wb;
#pragma unroll
        for (int t = 0; t < 8; t++) {
            int c = tid + t * 256;          // 0..2047
            int row = c >> 3, cc = c & 7;
            bool v = (m0 + row) < NN;
            size_t g = (size_t)(m0 + row) * 1024 + k0 + cc * 8;
            cpa16(buf + SWZ((uint32_t)(row * 128 + cc * 16)), ah + g, v);
        }
#pragma unroll
        for (int t = 0; t < 4; t++) {
            int c = tid + t * 256;          // 0..1023
            int row = c >> 3, cc = c & 7;
            size_t g = (size_t)(n0 + row) * 3072 + wk + cc * 8;
            cpa16(buf + OFF_B + SWZ((uint32_t)(row * 128 + cc * 16)), wt + g, true);
        }
    };

    issue(0);
    CP_COMMIT();
    if (nst > 1) { issue(1); CP_COMMIT(); }

    for (int st = 0; st < nst; st++) {
        if (st + 2 < nst) {
            issue(st + 2);
            CP_COMMIT();
            CP_WAIT(2);
        } else if (st + 1 < nst) {
            CP_WAIT(1);
        } else {
            CP_WAIT(0);
        }
        __syncthreads();
        const uint32_t buf = smb + (uint32_t)(st % 3) * STAGE;

#pragma unroll
        for (int kk = 0; kk < 4; kk++) {
            const uint32_t kb = (uint32_t)(kk * 32);
            uint32_t ah[4][4];
#pragma unroll
            for (int mi = 0; mi < 4; mi++) {
                uint32_t ad = buf + SWZ((uint32_t)((wm + mi * 16) * 128) + kb + a_off);
                ldsm4(ah[mi], ad);
            }
#pragma unroll
            for (int g = 0; g < 4; g++) {
                uint32_t bd = buf + OFF_B +
                    SWZ((uint32_t)((wn + g * 16) * 128) + kb + b_off);
                uint32_t bh[4];
                ldsm4(bh, bd);
#pragma unroll
                for (int mi = 0; mi < 4; mi++) {
#pragma unroll
                    for (int f = 0; f < 2; f++)
                        mma_fp16(acc[mi][2 * g + f], ah[mi], bh + 2 * f);
                }
            }
        }
        __syncthreads();
    }

    // ---- fused epilogue ----
    const int gq = lane >> 2, tq = lane & 3;
#pragma unroll
    for (int mi = 0; mi < 4; mi++) {
#pragma unroll
        for (int hh = 0; hh < 2; hh++) {
            int r = m0 + wm + mi * 16 + gq + hh * 8;
            if (r >= NN) continue;
#pragma unroll
            for (int nf = 0; nf < 8; nf++) {
                int col = n0 + wn + nf * 8 + tq * 2;
                float v0 = acc[mi][nf][2 * hh];
                float v1 = acc[mi][nf][2 * hh + 1];
                size_t o = (size_t)r * 1024 + col;
                if (EPI == 0) {
                    *(float2*)(C + o) = make_float2(v0, v1);
                } else if (EPI == 1) {
                    float2 b1 = *(const float2*)(ea.b1 + col);
                    float2 b2 = *(const float2*)(ea.b2 + col);
                    float z0 = sigm(v0 + b1.x + b2.x);
                    float z1 = sigm(v1 + b1.y + b2.y);
                    *(float2*)(C + o) = make_float2(z0, z1);
                } else if (EPI == 2) {
                    float2 b1 = *(const float2*)(ea.b1 + col);
                    float2 b2 = *(const float2*)(ea.b2 + col);
                    float2 hv = *(const float2*)(ea.Hin + o);
                    float hr0 = hv.x * sigm(v0 + b1.x + b2.x);
                    float hr1 = hv.y * sigm(v1 + b1.y + b2.y);
                    *(float2*)(ea.hr_f32 + o) = make_float2(hr0, hr1);
                    __half2 h = __floats2half2_rn(hr0, hr1);
                    *(uint32_t*)(ea.hr_hi + o) = *(uint32_t*)&h;
                } else {
                    float2 b1 = *(const float2*)(ea.b1 + col);
                    float2 b2 = *(const float2*)(ea.b2 + col);
                    float2 hp = *(const float2*)(C + o);
                    float2 zv = *(const float2*)(ea.Zin + o);
                    float2 hv = *(const float2*)(ea.Hin + o);
                    float t0 = tanhf(v0 + hp.x + b1.x + b2.x);
                    float t1 = tanhf(v1 + hp.y + b1.y + b2.y);
                    float o0 = zv.x * hv.x + (1.f - zv.x) * t0;
                    float o1 = zv.y * hv.y + (1.f - zv.y) * t1;
                    *(float2*)(ea.outp + o) = make_float2(o0, o1);
                }
            }
        }
    }
}

// ===================== launch ===============================================
extern "C" void kernel_launch(void* const* d_in, const int* in_sizes, int n_in,
                              void* d_out, int out_size) {
    const float* x   = (const float*)d_in[0];
    const float* H   = (const float*)d_in[1];
    const int*   ei  = (const int*)d_in[2];
    const int*   src = ei;
    const int*   dst = ei + EE;
    const float* ew  = (const float*)d_in[3];
    const float* Wxz = (const float*)d_in[4];
    const float* bxz = (const float*)d_in[5];
    const float* Whz = (const float*)d_in[6];
    const float* bhz = (const float*)d_in[7];
    const float* Wxr = (const float*)d_in[8];
    const float* bxr = (const float*)d_in[9];
    const float* Whr = (const float*)d_in[10];
    const float* bhr = (const float*)d_in[11];
    const float* Wxh = (const float*)d_in[12];
    const float* bxh = (const float*)d_in[13];
    const float* Whh = (const float*)d_in[14];
    const float* bhh = (const float*)d_in[15];
    float* out = (float*)d_out;

    float *T2h, *Zp, *Hp;
    cudaGetSymbolAddress((void**)&T2h, g_T2h);
    cudaGetSymbolAddress((void**)&Zp,  g_Zp);
    cudaGetSymbolAddress((void**)&Hp,  g_Hp);

    __half *hX, *h1X, *h2X, *hH, *h1H, *h2H, *hR, *h1R, *h2R, *Wt;
    cudaGetSymbolAddress((void**)&hX,  g_hX);
    cudaGetSymbolAddress((void**)&h1X, g_h1X);
    cudaGetSymbolAddress((void**)&h2X, g_h2X);
    cudaGetSymbolAddress((void**)&hH,  g_hH);
    cudaGetSymbolAddress((void**)&h1H, g_h1H);
    cudaGetSymbolAddress((void**)&h2H, g_h2H);
    cudaGetSymbolAddress((void**)&hR,  g_hR);
    cudaGetSymbolAddress((void**)&h1R, g_h1R);
    cudaGetSymbolAddress((void**)&h2R, g_h2R);
    cudaGetSymbolAddress((void**)&Wt,  g_Wt);

    cudaFuncSetAttribute(k_gemm3<0>,
        cudaFuncAttributeMaxDynamicSharedMemorySize, GEMM_SMEM);
    cudaFuncSetAttribute(k_gemm3<1>,
        cudaFuncAttributeMaxDynamicSharedMemorySize, GEMM_SMEM);
    cudaFuncSetAttribute(k_gemm3<2>,
        cudaFuncAttributeMaxDynamicSharedMemorySize, GEMM_SMEM);
    cudaFuncSetAttribute(k_gemm3<3>,
        cudaFuncAttributeMaxDynamicSharedMemorySize, GEMM_SMEM);

    const int NB_N = (NN + 255) / 256;
    const int NB_E = (EE + 255) / 256;
    const int NB_F4 = (int)(((size_t)NN * CC / 4 + 255) / 256);

    // normalization + CSR
    k_zero<<<NB_N, 256>>>();
    k_deg <<<NB_E, 256>>>(src, dst, ew);
    k_dis <<<NB_N, 256>>>();
    k_scan<<<1, 1024>>>();
    k_fill<<<NB_E, 256>>>(src, dst, ew);

    // weight transpose + fp16 (order: Wxz, Whz, Wxr, Whr, Wxh, Whh)
    WPtrs wp;
    wp.w[0] = Wxz; wp.w[1] = Whz; wp.w[2] = Wxr;
    wp.w[3] = Whr; wp.w[4] = Wxh; wp.w[5] = Whh;
    k_cvtW<<<dim3(96, 32, 6), 256>>>(wp, Wt);

    // x, H fp16 converts
    k_cvtA<<<NB_F4, 256>>>(x, hX);
    k_cvtA<<<NB_F4, 256>>>(H, hH);

    // Chebyshev recursions (fp16 gather, fp32 accum, fp16 out)
    k_lap16<false><<<NN, 256>>>(hX,  nullptr, h1X);
    k_lap16<true> <<<NN, 256>>>(h1X, x,       h2X);
    k_lap16<false><<<NN, 256>>>(hH,  nullptr, h1H);
    k_lap16<true> <<<NN, 256>>>(h1H, H,       h2H);

    dim3 gg(1024 / 128, (NN + 255) / 256);   // (8, 79)

    SegPtrsH sXH;
    sXH.a[0] = hX;  sXH.a[1] = h1X; sXH.a[2] = h2X;
    sXH.a[3] = hH;  sXH.a[4] = h1H; sXH.a[5] = h2H;

    EpiArgs ez = {}; ez.b1 = bxz; ez.b2 = bhz;
    // Z = sigmoid(Xcat@Wxz + Hcat@Whz + b) -> Zp
    k_gemm3<1><<<gg, 256, GEMM_SMEM>>>(sXH, Wt, Wt + WSZ, Zp, 6, ez);

    EpiArgs er = {}; er.b1 = bxr; er.b2 = bhr; er.Hin = H;
    er.hr_hi = hR; er.hr_f32 = T2h;
    // R -> H*R: fp32 into T2h, fp16 into hR
    k_gemm3<2><<<gg, 256, GEMM_SMEM>>>(sXH, Wt + 2 * WSZ, Wt + 3 * WSZ,
                                       T2h, 6, er);

    EpiArgs ep = {};
    // Hp = Xcat @ Wxh
    k_gemm3<0><<<gg, 256, GEMM_SMEM>>>(sXH, Wt + 4 * WSZ, Wt + 4 * WSZ,
                                       Hp, 3, ep);

    // Chebyshev recursion for H*R
    k_lap16<false><<<NN, 256>>>(hR,  nullptr, h1R);
    k_lap16<true> <<<NN, 256>>>(h1R, T2h,     h2R);

    SegPtrsH sR;
    sR.a[0] = hR;  sR.a[1] = h1R; sR.a[2] = h2R;
    sR.a[3] = hR;  sR.a[4] = h1R; sR.a[5] = h2R;

    EpiArgs ef = {}; ef.b1 = bxh; ef.b2 = bhh; ef.Hin = H; ef.Zin = Zp;
    ef.outp = out;
    // out = Z*H + (1-Z)*tanh(Hp + HRcat@Whh + b)
    k_gemm3<3><<<gg, 256, GEMM_SMEM>>>(sR, Wt + 5 * WSZ, Wt + 5 * WSZ,
                                       Hp, 3, ef);
}

// round 12
// speedup vs baseline: 9.4314x; 1.3076x over previous
#include <cuda_runtime.h>
#include <cuda_fp16.h>
#include <math.h>
#include <stdint.h>

#define NN 20000
#define EE 160000
#define CC 1024

// ===================== helpers ==============================================
__device__ __forceinline__ uint32_t smem_to_u32(const void* p) {
    uint32_t a;
    asm("{ .reg .u64 t; cvta.to.shared.u64 t, %1; cvt.u32.u64 %0, t; }"
        : "=r"(a) : "l"(p));
    return a;
}

__device__ __forceinline__ uint32_t SWZ(uint32_t o) {
    return o ^ ((o >> 3) & 0x70);
}

__device__ __forceinline__ void ldsm4(uint32_t* r, uint32_t addr) {
    asm volatile("ldmatrix.sync.aligned.m8n8.x4.shared.b16 {%0,%1,%2,%3}, [%4];"
        : "=r"(r[0]), "=r"(r[1]), "=r"(r[2]), "=r"(r[3]) : "r"(addr));
}

__device__ __forceinline__ void mma_fp16(float* d, const uint32_t* a,
                                         const uint32_t* b) {
    asm volatile(
        "mma.sync.aligned.m16n8k16.row.col.f32.f16.f16.f32 "
        "{%0,%1,%2,%3},{%4,%5,%6,%7},{%8,%9},{%0,%1,%2,%3};"
        : "+f"(d[0]), "+f"(d[1]), "+f"(d[2]), "+f"(d[3])
        : "r"(a[0]), "r"(a[1]), "r"(a[2]), "r"(a[3]), "r"(b[0]), "r"(b[1]));
}

__device__ __forceinline__ void cpa16(uint32_t dst, const void* src, bool valid) {
    asm volatile("cp.async.cg.shared.global [%0], [%1], 16, %2;"
        :: "r"(dst), "l"(src), "r"(valid ? 16 : 0));
}
#define CP_COMMIT() asm volatile("cp.async.commit_group;" ::: "memory")
#define CP_WAIT(n)  asm volatile("cp.async.wait_group %0;" :: "n"(n) : "memory")

__device__ __forceinline__ float sigm(float x) { return 1.f / (1.f + expf(-x)); }

// ===================== scratch (__device__ globals) =========================
__device__ __align__(16) float g_deg[NN];
__device__ __align__(16) float g_dis[NN];
__device__ int   g_cnt[NN];
__device__ int   g_rp[NN + 1];
__device__ int   g_cur[NN];
__device__ int   g_col[EE];
__device__ __align__(16) float g_val[EE];

__device__ __align__(16) float g_T2h[(size_t)NN * CC];   // H*R fp32 (sub term)
__device__ __align__(16) float g_Zp[(size_t)NN * CC];    // Z (post-sigmoid)
__device__ __align__(16) float g_Hp[(size_t)NN * CC];    // H-candidate pre-act

// fp16 activation buffers
#define ABUF ((size_t)NN * CC)
__device__ __align__(16) __half g_hX[ABUF];
__device__ __align__(16) __half g_h1X[ABUF];
__device__ __align__(16) __half g_h2X[ABUF];
__device__ __align__(16) __half g_hH[ABUF];
__device__ __align__(16) __half g_h1H[ABUF];
__device__ __align__(16) __half g_h2H[ABUF];
__device__ __align__(16) __half g_hR[ABUF];
__device__ __align__(16) __half g_h1R[ABUF];
__device__ __align__(16) __half g_h2R[ABUF];

// transposed fp16 weights: 6 x [1024 n][3072 k]
#define WSZ ((size_t)1024 * 3072)
__device__ __align__(16) __half g_Wt[6 * WSZ];

// ===================== graph normalization + CSR build ======================
__global__ void k_zero() {
    int i = blockIdx.x * 256 + threadIdx.x;
    if (i < NN) { g_deg[i] = 0.0f; g_cnt[i] = 0; }
}

__global__ void k_deg(const int* __restrict__ src, const int* __restrict__ dst,
                      const float* __restrict__ ew) {
    int e = blockIdx.x * 256 + threadIdx.x;
    if (e < EE) {
        int s = src[e], d = dst[e];
        float w = (s == d) ? 0.0f : ew[e];
        atomicAdd(&g_deg[s], w);
        atomicAdd(&g_cnt[d], 1);
    }
}

__global__ void k_dis() {
    int i = blockIdx.x * 256 + threadIdx.x;
    if (i < NN) {
        float d = g_deg[i];
        g_dis[i] = (d > 0.0f) ? rsqrtf(d) : 0.0f;
    }
}

__global__ void k_scan() {
    __shared__ int wsum[32];
    __shared__ int sh_carry;
    int tid = threadIdx.x;
    int lane = tid & 31, wid = tid >> 5;
    if (tid == 0) sh_carry = 0;
    __syncthreads();
    for (int base = 0; base < NN; base += 1024) {
        int i = base + tid;
        int v = (i < NN) ? g_cnt[i] : 0;
        int inc = v;
#pragma unroll
        for (int off = 1; off < 32; off <<= 1) {
            int t = __shfl_up_sync(0xFFFFFFFFu, inc, off);
            if (lane >= off) inc += t;
        }
        if (lane == 31) wsum[wid] = inc;
        __syncthreads();
        if (wid == 0) {
            int wv = wsum[lane];
            int winc = wv;
#pragma unroll
            for (int off = 1; off < 32; off <<= 1) {
                int t = __shfl_up_sync(0xFFFFFFFFu, winc, off);
                if (lane >= off) winc += t;
            }
            wsum[lane] = winc - wv;
        }
        __syncthreads();
        int excl = sh_carry + wsum[wid] + inc - v;
        if (i < NN) { g_rp[i] = excl; g_cur[i] = excl; }
        __syncthreads();
        if (tid == 1023) sh_carry = excl + v;
        __syncthreads();
    }
    if (tid == 0) g_rp[NN] = sh_carry;
}

__global__ void k_fill(const int* __restrict__ src, const int* __restrict__ dst,
                       const float* __restrict__ ew) {
    int e = blockIdx.x * 256 + threadIdx.x;
    if (e < EE) {
        int s = src[e], d = dst[e];
        float w = (s == d) ? 0.0f : ew[e];
        float nw = -g_dis[s] * w * g_dis[d];
        int pos = atomicAdd(&g_cur[d], 1);
        g_col[pos] = s;
        g_val[pos] = nw;
    }
}

// ===================== converts =============================================
__global__ void k_cvtA(const float* __restrict__ in, __half* __restrict__ hi) {
    size_t i = (size_t)blockIdx.x * 256 + threadIdx.x;
    if (i < (size_t)NN * CC / 4) {
        float4 v = *(const float4*)(in + i * 4);
        __half2 h0 = __floats2half2_rn(v.x, v.y);
        __half2 h1 = __floats2half2_rn(v.z, v.w);
        *(uint2*)(hi + i * 4) = make_uint2(*(uint32_t*)&h0, *(uint32_t*)&h1);
    }
}

struct WPtrs { const float* w[6]; };
__global__ void k_cvtW(WPtrs wp, __half* __restrict__ wt) {
    __shared__ float ts[32][33];
    int kb = blockIdx.x * 32;
    int nb = blockIdx.y * 32;
    const float* W = wp.w[blockIdx.z];
    int c = threadIdx.x & 31, r8 = threadIdx.x >> 5;
#pragma unroll
    for (int i = 0; i < 4; i++) {
        int kr = r8 + i * 8;
        ts[kr][c] = W[(size_t)(kb + kr) * 1024 + nb + c];
    }
    __syncthreads();
    __half* bh = wt + (size_t)blockIdx.z * WSZ;
#pragma unroll
    for (int i = 0; i < 4; i++) {
        int nr = r8 + i * 8;
        bh[(size_t)(nb + nr) * 3072 + kb + c] = __float2half(ts[c][nr]);
    }
}

// ============ Laplacian apply: fp16 gather, fp32 accum, fp16 out ============
template <bool CHEB2>
__global__ void k_lap16(const __half* __restrict__ in,
                        const float* __restrict__ sub,
                        __half* __restrict__ out) {
    int node = blockIdx.x;
    int c4 = threadIdx.x;
    int s = g_rp[node], e = g_rp[node + 1];
    float a0 = 0.f, a1 = 0.f, a2 = 0.f, a3 = 0.f;
    for (int i = s; i < e; i++) {
        float w = __ldg(&g_val[i]);
        int   c = __ldg(&g_col[i]);
        uint2 hv = *(const uint2*)(in + (size_t)c * CC + c4 * 4);
        __half2 p0 = *reinterpret_cast<__half2*>(&hv.x);
        __half2 p1 = *reinterpret_cast<__half2*>(&hv.y);
        float2 f0 = __half22float2(p0);
        float2 f1 = __half22float2(p1);
        a0 += w * f0.x; a1 += w * f0.y; a2 += w * f1.x; a3 += w * f1.y;
    }
    if (CHEB2) {
        float4 sb = *(const float4*)(sub + (size_t)node * CC + c4 * 4);
        a0 = 2.f * a0 - sb.x; a1 = 2.f * a1 - sb.y;
        a2 = 2.f * a2 - sb.z; a3 = 2.f * a3 - sb.w;
    }
    __half2 o0 = __floats2half2_rn(a0, a1);
    __half2 o1 = __floats2half2_rn(a2, a3);
    *(uint2*)(out + (size_t)node * CC + c4 * 4) =
        make_uint2(*(uint32_t*)&o0, *(uint32_t*)&o1);
}

// ===================== merged pipelined MMA GEMM ============================
// Per blockIdx.z job: acc[M,1024] = sum_seg Aseg @ W; fused epilogue by epi.
// CTA tile 128M x 128N, BK=64, 3-stage pipeline, 2 CTAs/SM.
// stage (32 KB): A[128][64] 16K | W[128n][64k] 16K
#define STAGE 32768u
#define OFF_B  16384u
#define GEMM_SMEM (3 * 32768)

struct SegPtrsH { const __half* a[6]; };
struct GJob {
    const __half* Wa; const __half* Wb;
    float* C;
    const float* b1; const float* b2;
    int nseg; int epi;   // 0 store, 1 Z, 2 R->H*R, 3 final mix
};
struct GParams {
    SegPtrsH sp;
    GJob job[3];
    const float* Hin; const float* Zin;
    __half* hr16; float* hr32;
    float* outp;
};

__global__ __launch_bounds__(256, 2)
void k_gemmM(GParams gp) {
    extern __shared__ __align__(1024) char sm[];
    const uint32_t smb = smem_to_u32(sm);
    const int tid = threadIdx.x;
    const int m0 = blockIdx.y * 128;
    const int n0 = blockIdx.x * 128;
    const GJob jb = gp.job[blockIdx.z];
    const int nst = jb.nseg * 16;

    const int warp = tid >> 5, lane = tid & 31;
    const int wm = (warp >> 1) * 32, wn = (warp & 1) * 64;
    const int lj = lane >> 3, lr = lane & 7;
    const uint32_t a_off = (uint32_t)(((lj & 1) * 8 + lr) * 128 + (lj >> 1) * 16);
    const uint32_t b_off = (uint32_t)(((lj >> 1) * 8 + lr) * 128 + (lj & 1) * 16);

    float acc[2][8][4];
#pragma unroll
    for (int a = 0; a < 2; a++)
#pragma unroll
        for (int b = 0; b < 8; b++)
#pragma unroll
            for (int c = 0; c < 4; c++) acc[a][b][c] = 0.f;

    auto issue = [&](int st) {
        const int seg = st >> 4;
        const int k0 = (st & 15) * 64;
        const int wk = (seg % 3) * 1024 + k0;
        const uint32_t buf = smb + (uint32_t)(st % 3) * STAGE;
        const __half* ah = gp.sp.a[seg];
        const __half* wt = (seg < 3) ? jb.Wa : jb.Wb;
#pragma unroll
        for (int t = 0; t < 4; t++) {
            int c = tid + t * 256;          // 0..1023
            int row = c >> 3, cc = c & 7;
            bool v = (m0 + row) < NN;
            size_t g = (size_t)(m0 + row) * 1024 + k0 + cc * 8;
            cpa16(buf + SWZ((uint32_t)(row * 128 + cc * 16)), ah + g, v);
        }
#pragma unroll
        for (int t = 0; t < 4; t++) {
            int c = tid + t * 256;          // 0..1023
            int row = c >> 3, cc = c & 7;
            size_t g = (size_t)(n0 + row) * 3072 + wk + cc * 8;
            cpa16(buf + OFF_B + SWZ((uint32_t)(row * 128 + cc * 16)), wt + g, true);
        }
    };

    issue(0);
    CP_COMMIT();
    issue(1);
    CP_COMMIT();

    for (int st = 0; st < nst; st++) {
        if (st + 2 < nst) {
            issue(st + 2);
            CP_COMMIT();
            CP_WAIT(2);
        } else if (st + 1 < nst) {
            CP_WAIT(1);
        } else {
            CP_WAIT(0);
        }
        __syncthreads();
        const uint32_t buf = smb + (uint32_t)(st % 3) * STAGE;

#pragma unroll
        for (int kk = 0; kk < 4; kk++) {
            const uint32_t kb = (uint32_t)(kk * 32);
            uint32_t ah[2][4];
#pragma unroll
            for (int mi = 0; mi < 2; mi++) {
                uint32_t ad = buf + SWZ((uint32_t)((wm + mi * 16) * 128) + kb + a_off);
                ldsm4(ah[mi], ad);
            }
#pragma unroll
            for (int g = 0; g < 4; g++) {
                uint32_t bd = buf + OFF_B +
                    SWZ((uint32_t)((wn + g * 16) * 128) + kb + b_off);
                uint32_t bh[4];
                ldsm4(bh, bd);
#pragma unroll
                for (int mi = 0; mi < 2; mi++) {
#pragma unroll
                    for (int f = 0; f < 2; f++)
                        mma_fp16(acc[mi][2 * g + f], ah[mi], bh + 2 * f);
                }
            }
        }
        __syncthreads();
    }

    // ---- fused epilogue ----
    const int gq = lane >> 2, tq = lane & 3;
    const int epi = jb.epi;
    float* C = jb.C;
#pragma unroll
    for (int mi = 0; mi < 2; mi++) {
#pragma unroll
        for (int hh = 0; hh < 2; hh++) {
            int r = m0 + wm + mi * 16 + gq + hh * 8;
            if (r >= NN) continue;
#pragma unroll
            for (int nf = 0; nf < 8; nf++) {
                int col = n0 + wn + nf * 8 + tq * 2;
                float v0 = acc[mi][nf][2 * hh];
                float v1 = acc[mi][nf][2 * hh + 1];
                size_t o = (size_t)r * 1024 + col;
                if (epi == 0) {
                    *(float2*)(C + o) = make_float2(v0, v1);
                } else if (epi == 1) {
                    float2 b1 = *(const float2*)(jb.b1 + col);
                    float2 b2 = *(const float2*)(jb.b2 + col);
                    float z0 = sigm(v0 + b1.x + b2.x);
                    float z1 = sigm(v1 + b1.y + b2.y);
                    *(float2*)(C + o) = make_float2(z0, z1);
                } else if (epi == 2) {
                    float2 b1 = *(const float2*)(jb.b1 + col);
                    float2 b2 = *(const float2*)(jb.b2 + col);
                    float2 hv = *(const float2*)(gp.Hin + o);
                    float hr0 = hv.x * sigm(v0 + b1.x + b2.x);
                    float hr1 = hv.y * sigm(v1 + b1.y + b2.y);
                    *(float2*)(gp.hr32 + o) = make_float2(hr0, hr1);
                    __half2 h = __floats2half2_rn(hr0, hr1);
                    *(uint32_t*)(gp.hr16 + o) = *(uint32_t*)&h;
                } else {
                    float2 b1 = *(const float2*)(jb.b1 + col);
                    float2 b2 = *(const float2*)(jb.b2 + col);
                    float2 hp = *(const float2*)(C + o);
                    float2 zv = *(const float2*)(gp.Zin + o);
                    float2 hv = *(const float2*)(gp.Hin + o);
                    float t0 = tanhf(v0 + hp.x + b1.x + b2.x);
                    float t1 = tanhf(v1 + hp.y + b1.y + b2.y);
                    float o0 = zv.x * hv.x + (1.f - zv.x) * t0;
                    float o1 = zv.y * hv.y + (1.f - zv.y) * t1;
                    *(float2*)(gp.outp + o) = make_float2(o0, o1);
                }
            }
        }
    }
}

// ===================== launch ===============================================
extern "C" void kernel_launch(void* const* d_in, const int* in_sizes, int n_in,
                              void* d_out, int out_size) {
    const float* x   = (const float*)d_in[0];
    const float* H   = (const float*)d_in[1];
    const int*   ei  = (const int*)d_in[2];
    const int*   src = ei;
    const int*   dst = ei + EE;
    const float* ew  = (const float*)d_in[3];
    const float* Wxz = (const float*)d_in[4];
    const float* bxz = (const float*)d_in[5];
    const float* Whz = (const float*)d_in[6];
    const float* bhz = (const float*)d_in[7];
    const float* Wxr = (const float*)d_in[8];
    const float* bxr = (const float*)d_in[9];
    const float* Whr = (const float*)d_in[10];
    const float* bhr = (const float*)d_in[11];
    const float* Wxh = (const float*)d_in[12];
    const float* bxh = (const float*)d_in[13];
    const float* Whh = (const float*)d_in[14];
    const float* bhh = (const float*)d_in[15];
    float* out = (float*)d_out;

    float *T2h, *Zp, *Hp;
    cudaGetSymbolAddress((void**)&T2h, g_T2h);
    cudaGetSymbolAddress((void**)&Zp,  g_Zp);
    cudaGetSymbolAddress((void**)&Hp,  g_Hp);

    __half *hX, *h1X, *h2X, *hH, *h1H, *h2H, *hR, *h1R, *h2R, *Wt;
    cudaGetSymbolAddress((void**)&hX,  g_hX);
    cudaGetSymbolAddress((void**)&h1X, g_h1X);
    cudaGetSymbolAddress((void**)&h2X, g_h2X);
    cudaGetSymbolAddress((void**)&hH,  g_hH);
    cudaGetSymbolAddress((void**)&h1H, g_h1H);
    cudaGetSymbolAddress((void**)&h2H, g_h2H);
    cudaGetSymbolAddress((void**)&hR,  g_hR);
    cudaGetSymbolAddress((void**)&h1R, g_h1R);
    cudaGetSymbolAddress((void**)&h2R, g_h2R);
    cudaGetSymbolAddress((void**)&Wt,  g_Wt);

    cudaFuncSetAttribute(k_gemmM,
        cudaFuncAttributeMaxDynamicSharedMemorySize, GEMM_SMEM);

    const int NB_N = (NN + 255) / 256;
    const int NB_E = (EE + 255) / 256;
    const int NB_F4 = (int)(((size_t)NN * CC / 4 + 255) / 256);

    // normalization + CSR
    k_zero<<<NB_N, 256>>>();
    k_deg <<<NB_E, 256>>>(src, dst, ew);
    k_dis <<<NB_N, 256>>>();
    k_scan<<<1, 1024>>>();
    k_fill<<<NB_E, 256>>>(src, dst, ew);

    // weight transpose + fp16 (order: Wxz, Whz, Wxr, Whr, Wxh, Whh)
    WPtrs wp;
    wp.w[0] = Wxz; wp.w[1] = Whz; wp.w[2] = Wxr;
    wp.w[3] = Whr; wp.w[4] = Wxh; wp.w[5] = Whh;
    k_cvtW<<<dim3(96, 32, 6), 256>>>(wp, Wt);

    // x, H fp16 converts
    k_cvtA<<<NB_F4, 256>>>(x, hX);
    k_cvtA<<<NB_F4, 256>>>(H, hH);

    // Chebyshev recursions (fp16 gather, fp32 accum, fp16 out)
    k_lap16<false><<<NN, 256>>>(hX,  nullptr, h1X);
    k_lap16<true> <<<NN, 256>>>(h1X, x,       h2X);
    k_lap16<false><<<NN, 256>>>(hH,  nullptr, h1H);
    k_lap16<true> <<<NN, 256>>>(h1H, H,       h2H);

    const int MT = (NN + 127) / 128;         // 157 m-tiles

    // merged Z / R / Hp GEMM (one launch, blockIdx.z = job)
    GParams gpz;
    gpz.sp.a[0] = hX;  gpz.sp.a[1] = h1X; gpz.sp.a[2] = h2X;
    gpz.sp.a[3] = hH;  gpz.sp.a[4] = h1H; gpz.sp.a[5] = h2H;
    gpz.Hin = H; gpz.Zin = nullptr;
    gpz.hr16 = hR; gpz.hr32 = T2h; gpz.outp = nullptr;
    // job 0: Z = sigmoid(Xcat@Wxz + Hcat@Whz + b) -> Zp
    gpz.job[0] = {Wt, Wt + WSZ, Zp, bxz, bhz, 6, 1};
    // job 1: R -> H*R (fp32 T2h + fp16 hR)
    gpz.job[1] = {Wt + 2 * WSZ, Wt + 3 * WSZ, nullptr, bxr, bhr, 6, 2};
    // job 2: Hp = Xcat @ Wxh
    gpz.job[2] = {Wt + 4 * WSZ, Wt + 4 * WSZ, Hp, nullptr, nullptr, 3, 0};
    k_gemmM<<<dim3(8, MT, 3), 256, GEMM_SMEM>>>(gpz);

    // Chebyshev recursion for H*R
    k_lap16<false><<<NN, 256>>>(hR,  nullptr, h1R);
    k_lap16<true> <<<NN, 256>>>(h1R, T2h,     h2R);

    // final GEMM: out = Z*H + (1-Z)*tanh(Hp + HRcat@Whh + b)
    GParams gpf;
    gpf.sp.a[0] = hR;  gpf.sp.a[1] = h1R; gpf.sp.a[2] = h2R;
    gpf.sp.a[3] = hR;  gpf.sp.a[4] = h1R; gpf.sp.a[5] = h2R;
    gpf.Hin = H; gpf.Zin = Zp;
    gpf.hr16 = nullptr; gpf.hr32 = nullptr; gpf.outp = out;
    gpf.job[0] = {Wt + 5 * WSZ, Wt + 5 * WSZ, Hp, bxh, bhh, 3, 3};
    gpf.job[1] = gpf.job[0];
    gpf.job[2] = gpf.job[0];
    k_gemmM<<<dim3(8, MT, 1), 256, GEMM_SMEM>>>(gpf);
}